// round 2
// baseline (speedup 1.0000x reference)
#include <cuda_runtime.h>
#include <math.h>

// ---------------------------------------------------------------------------
// MVAEdecoder: blended-expert MLP.
//   g  = concat(x,z)                     [4096, 864]
//   h1 = elu(g @ Wg1^T + bg1)            [4096, 128]
//   h2 = elu(h1 @ Wg2^T + bg2)           [4096, 128]
//   bc = softmax(h2 @ Wg3^T + bg3)       [4096, 8]
//   h  = elu(blend(bc, concat(x,z), W0, b0))   [4096, 1024]
//   h  = elu(blend(bc, concat(h,z), W1, b1))
//   h  = elu(blend(bc, concat(h,z), W2, b2))
//   out =     blend(bc, h,           W3, b3)   [4096, 768]
//
// blend(bc, inp, W, b)[b,o] = sum_e bc[b,e] * (W[e,o,:]·inp[b,:] + b[e,o])
//                           = GEMM with K' = E*IN, A'[b, e*IN+k] = bc[b,e]*inp[b,k]
// The bc scaling is applied during the A smem load (each K-tile of width 16
// lies inside a single expert since IN % 16 == 0 for every layer).
// ---------------------------------------------------------------------------

#define MB 4096
#define XD 800
#define ZD 64
#define HD 1024
#define OD 768
#define GHD 128
#define NE 8

// scratch (static __device__ arrays: allocation-free per harness rules)
__device__ __align__(16) float g_G [MB * (XD + ZD)];   // concat(x,z)  [4096,864]
__device__ __align__(16) float g_H1[MB * GHD];
__device__ __align__(16) float g_H2[MB * GHD];
__device__ __align__(16) float g_BC[MB * NE];
__device__ __align__(16) float g_HA[MB * (HD + ZD)];   // [4096,1088] (z in cols 1024..1087)
__device__ __align__(16) float g_HB[MB * (HD + ZD)];

// ---------------------------------------------------------------------------
// prep: build G = concat(x,z) and pre-fill the z columns of HA / HB
// ---------------------------------------------------------------------------
__global__ void prep_kernel(const float* __restrict__ x, const float* __restrict__ z,
                            float* __restrict__ G, float* __restrict__ HA,
                            float* __restrict__ HB) {
    int i = blockIdx.x * blockDim.x + threadIdx.x;
    const int totG = MB * (XD + ZD);
    if (i < totG) {
        int b = i / (XD + ZD), c = i - b * (XD + ZD);
        G[i] = (c < XD) ? x[b * XD + c] : z[b * ZD + (c - XD)];
    }
    const int totZ = MB * ZD;
    if (i < totZ) {
        int b = i / ZD, c = i - b * ZD;
        float v = z[i];
        HA[b * (HD + ZD) + HD + c] = v;
        HB[b * (HD + ZD) + HD + c] = v;
    }
}

// ---------------------------------------------------------------------------
// Tiled fp32 GEMM with optional per-(row,expert) A-scaling + blended bias + ELU.
//   C[m, n] = act( sum_{e,k} (bc[m,e]*A[m,k]) * W[e, n, k]  +  sum_e bc[m,e]*bias[e,n] )
// HAS_BC=false => E=1, no scaling, bias = bias[n].
// BM=BN=128, BK=16, 256 threads, 8x8 per thread. Requires M%128==0, Nout%128==0,
// IN%16==0, lda%4==0.
// ---------------------------------------------------------------------------
#define BMT 128
#define BNT 128
#define BKT 16

template <bool HAS_BC>
__global__ __launch_bounds__(256, 2)
void moe_gemm_kernel(const float* __restrict__ A, int lda, int IN,
                     const float* __restrict__ W,      // [E, Nout, IN]
                     const float* __restrict__ bias,   // [E, Nout]
                     const float* __restrict__ bc,     // [M, 8] (HAS_BC only)
                     int Nout,
                     float* __restrict__ C, int ldc, int applyElu) {
    __shared__ float As[BKT][BMT];
    __shared__ float Bs[BKT][BNT];

    const int tid = threadIdx.x;            // 0..255
    const int tx = tid & 15;                 // 0..15
    const int ty = tid >> 4;                 // 0..15
    const int mBase = blockIdx.y * BMT;
    const int nBase = blockIdx.x * BNT;

    const int E = HAS_BC ? NE : 1;
    const int Ktot = E * IN;

    // loader lane mapping (512 float4 per tile per operand; 2 per thread)
    const int aRow = tid >> 2;               // 0..63
    const int aVec = (tid & 3) << 2;          // 0,4,8,12

    float acc[8][8];
#pragma unroll
    for (int i = 0; i < 8; i++)
#pragma unroll
        for (int j = 0; j < 8; j++) acc[i][j] = 0.f;

    int e = 0, kin = 0;
    for (int k0 = 0; k0 < Ktot; k0 += BKT) {
        // ---- load A tile (scaled by bc) ----
#pragma unroll
        for (int rr = 0; rr < 2; rr++) {
            int r = aRow + rr * 64;
            int grow = mBase + r;
            float4 v = *reinterpret_cast<const float4*>(A + (size_t)grow * lda + kin + aVec);
            float s = 1.f;
            if (HAS_BC) s = __ldg(bc + grow * NE + e);
            As[aVec + 0][r] = v.x * s;
            As[aVec + 1][r] = v.y * s;
            As[aVec + 2][r] = v.z * s;
            As[aVec + 3][r] = v.w * s;
        }
        // ---- load W tile ----
#pragma unroll
        for (int rr = 0; rr < 2; rr++) {
            int o = aRow + rr * 64;
            int go = nBase + o;
            float4 v = *reinterpret_cast<const float4*>(
                W + ((size_t)e * Nout + go) * IN + kin + aVec);
            Bs[aVec + 0][o] = v.x;
            Bs[aVec + 1][o] = v.y;
            Bs[aVec + 2][o] = v.z;
            Bs[aVec + 3][o] = v.w;
        }
        __syncthreads();

#pragma unroll
        for (int k = 0; k < BKT; k++) {
            float4 a0 = *reinterpret_cast<const float4*>(&As[k][ty * 8]);
            float4 a1 = *reinterpret_cast<const float4*>(&As[k][ty * 8 + 4]);
            float4 b0 = *reinterpret_cast<const float4*>(&Bs[k][tx * 8]);
            float4 b1 = *reinterpret_cast<const float4*>(&Bs[k][tx * 8 + 4]);
            float av[8] = {a0.x, a0.y, a0.z, a0.w, a1.x, a1.y, a1.z, a1.w};
            float bv[8] = {b0.x, b0.y, b0.z, b0.w, b1.x, b1.y, b1.z, b1.w};
#pragma unroll
            for (int i = 0; i < 8; i++)
#pragma unroll
                for (int j = 0; j < 8; j++) acc[i][j] = fmaf(av[i], bv[j], acc[i][j]);
        }
        __syncthreads();

        kin += BKT;
        if (kin == IN) { kin = 0; e++; }
    }

    // ---- epilogue: blended bias + optional ELU ----
#pragma unroll
    for (int i = 0; i < 8; i++) {
        int grow = mBase + ty * 8 + i;
        float bcv[NE];
        if (HAS_BC) {
#pragma unroll
            for (int ee = 0; ee < NE; ee++) bcv[ee] = __ldg(bc + grow * NE + ee);
        }
#pragma unroll
        for (int j = 0; j < 8; j++) {
            int gcol = nBase + tx * 8 + j;
            float bb;
            if (HAS_BC) {
                bb = 0.f;
#pragma unroll
                for (int ee = 0; ee < NE; ee++)
                    bb = fmaf(bcv[ee], __ldg(bias + ee * Nout + gcol), bb);
            } else {
                bb = __ldg(bias + gcol);
            }
            float v = acc[i][j] + bb;
            if (applyElu) v = (v > 0.f) ? v : expm1f(v);
            C[(size_t)grow * ldc + gcol] = v;
        }
    }
}

// ---------------------------------------------------------------------------
// gate3 + softmax: bc[b,e] = softmax_e( h2[b,:]·Wg3[e,:] + bg3[e] )
// one warp per row
// ---------------------------------------------------------------------------
__global__ void gate3_softmax_kernel(const float* __restrict__ H2,
                                     const float* __restrict__ Wg3,
                                     const float* __restrict__ bg3,
                                     float* __restrict__ BC) {
    int warp = (blockIdx.x * blockDim.x + threadIdx.x) >> 5;
    int lane = threadIdx.x & 31;
    if (warp >= MB) return;

    const float* h = H2 + (size_t)warp * GHD;
    float hv[4];
#pragma unroll
    for (int t = 0; t < 4; t++) hv[t] = h[lane + 32 * t];

    float s[NE];
#pragma unroll
    for (int eidx = 0; eidx < NE; eidx++) {
        float p = 0.f;
#pragma unroll
        for (int t = 0; t < 4; t++)
            p = fmaf(hv[t], __ldg(Wg3 + eidx * GHD + lane + 32 * t), p);
#pragma unroll
        for (int off = 16; off > 0; off >>= 1) p += __shfl_xor_sync(0xFFFFFFFFu, p, off);
        s[eidx] = p + __ldg(bg3 + eidx);
    }
    float mx = s[0];
#pragma unroll
    for (int eidx = 1; eidx < NE; eidx++) mx = fmaxf(mx, s[eidx]);
    float sum = 0.f;
#pragma unroll
    for (int eidx = 0; eidx < NE; eidx++) { s[eidx] = expf(s[eidx] - mx); sum += s[eidx]; }
    float inv = 1.f / sum;
    if (lane < NE) BC[(size_t)warp * NE + lane] = s[lane] * inv;
}

// ---------------------------------------------------------------------------
extern "C" void kernel_launch(void* const* d_in, const int* in_sizes, int n_in,
                              void* d_out, int out_size) {
    const float* x   = (const float*)d_in[0];
    const float* z   = (const float*)d_in[1];
    const float* Wg1 = (const float*)d_in[2];
    const float* bg1 = (const float*)d_in[3];
    const float* Wg2 = (const float*)d_in[4];
    const float* bg2 = (const float*)d_in[5];
    const float* Wg3 = (const float*)d_in[6];
    const float* bg3 = (const float*)d_in[7];
    const float* W0  = (const float*)d_in[8];
    const float* b0  = (const float*)d_in[9];
    const float* W1  = (const float*)d_in[10];
    const float* b1  = (const float*)d_in[11];
    const float* W2  = (const float*)d_in[12];
    const float* b2  = (const float*)d_in[13];
    const float* W3  = (const float*)d_in[14];
    const float* b3  = (const float*)d_in[15];
    float* out = (float*)d_out;

    float *G, *H1, *H2, *BC, *HA, *HB;
    cudaGetSymbolAddress((void**)&G,  g_G);
    cudaGetSymbolAddress((void**)&H1, g_H1);
    cudaGetSymbolAddress((void**)&H2, g_H2);
    cudaGetSymbolAddress((void**)&BC, g_BC);
    cudaGetSymbolAddress((void**)&HA, g_HA);
    cudaGetSymbolAddress((void**)&HB, g_HB);

    const int GW = XD + ZD;   // 864
    const int HW = HD + ZD;   // 1088

    // prep: concat + z-column fill
    {
        int tot = MB * GW;
        prep_kernel<<<(tot + 255) / 256, 256>>>(x, z, G, HA, HB);
    }

    // gate layer 1: [4096,864] @ Wg1^T -> [4096,128], elu
    moe_gemm_kernel<false><<<dim3(GHD / BNT, MB / BMT), 256>>>(
        G, GW, GW, Wg1, bg1, nullptr, GHD, H1, GHD, 1);
    // gate layer 2: [4096,128] @ Wg2^T -> [4096,128], elu
    moe_gemm_kernel<false><<<dim3(GHD / BNT, MB / BMT), 256>>>(
        H1, GHD, GHD, Wg2, bg2, nullptr, GHD, H2, GHD, 1);
    // gate layer 3 + softmax -> BC [4096,8]
    gate3_softmax_kernel<<<(MB * 32 + 255) / 256, 256>>>(H2, Wg3, bg3, BC);

    // expert layer 0: inp = G [4096,864], K' = 8*864 = 6912 -> HA[:, :1024], elu
    moe_gemm_kernel<true><<<dim3(HD / BNT, MB / BMT), 256>>>(
        G, GW, GW, W0, b0, BC, HD, HA, HW, 1);
    // expert layer 1: inp = HA [4096,1088], K' = 8*1088 -> HB[:, :1024], elu
    moe_gemm_kernel<true><<<dim3(HD / BNT, MB / BMT), 256>>>(
        HA, HW, HW, W1, b1, BC, HD, HB, HW, 1);
    // expert layer 2: inp = HB -> HA[:, :1024], elu
    moe_gemm_kernel<true><<<dim3(HD / BNT, MB / BMT), 256>>>(
        HB, HW, HW, W2, b2, BC, HD, HA, HW, 1);
    // expert layer 3: inp = HA cols 0..1023 (IN=1024, lda=1088) -> out [4096,768], no act
    moe_gemm_kernel<true><<<dim3(OD / BNT, MB / BMT), 256>>>(
        HA, HW, HD, W3, b3, BC, OD, out, OD, 0);
}

// round 4
// speedup vs baseline: 3.1996x; 3.1996x over previous
#include <cuda_runtime.h>
#include <cuda_fp16.h>
#include <math.h>
#include <stdint.h>

// ===========================================================================
// MVAEdecoder via HMMA (mma.sync m16n8k16 fp16, fp32 accum), 3-term split.
// blend(bc,inp,W,b)[m,o] = sum_e bc[m,e]*(W[e,o,:]·inp[m,:]) + sum_e bc[m,e]*b[e,o]
//  => GEMM with K' = E*IN; A'[m, e*IN+k] = bc[m,e]*inp[m,k] (pre-split pass).
// a = ah+al, w = wh+wl (fp16 each); D += ah*wh + ah*wl + al*wh  (al*wl ~ 2^-22)
// ===========================================================================

#define MB 4096
#define XD 800
#define ZD 64
#define HD 1024
#define OD 768
#define GHD 128
#define NE 8
#define GW (XD + ZD)   // 864
#define HW (HD + ZD)   // 1088

#define KP0 (NE * GW)  // 6912
#define KP1 (NE * HW)  // 8704
#define KP3 (NE * HD)  // 8192

// ---------------- static device scratch ----------------
__device__ __align__(128) float g_G [MB * GW];
__device__ __align__(128) float g_H1[MB * GHD];
__device__ __align__(128) float g_H2[MB * GHD];
__device__ __align__(128) float g_BC[MB * NE];
__device__ __align__(128) float g_HA[MB * HW];
__device__ __align__(128) float g_HB[MB * HW];

// pre-split A' (bc-scaled, expert-replicated), fp16 hi/lo, max K' = 8704
__device__ __align__(128) __half g_Ah[MB * KP1];
__device__ __align__(128) __half g_Al[MB * KP1];

// fp16 hi/lo weight copies, layout [Nout][K'=NE*IN]
__device__ __align__(128) __half g_W0h[HD * KP0];
__device__ __align__(128) __half g_W0l[HD * KP0];
__device__ __align__(128) __half g_W1h[HD * KP1];
__device__ __align__(128) __half g_W1l[HD * KP1];
__device__ __align__(128) __half g_W2h[HD * KP1];
__device__ __align__(128) __half g_W2l[HD * KP1];
__device__ __align__(128) __half g_W3h[OD * KP3];
__device__ __align__(128) __half g_W3l[OD * KP3];

// ---------------- PTX helpers ----------------
__device__ __forceinline__ uint32_t smem_u32(const void* p) {
    uint32_t a;
    asm("{ .reg .u64 t; cvta.to.shared.u64 t, %1; cvt.u32.u64 %0, t; }" : "=r"(a) : "l"(p));
    return a;
}

__device__ __forceinline__ void cp_async16(uint32_t dst, const void* src) {
    asm volatile("cp.async.cg.shared.global [%0], [%1], 16;" :: "r"(dst), "l"(src) : "memory");
}
#define CP_COMMIT() asm volatile("cp.async.commit_group;" ::: "memory")
#define CP_WAIT1()  asm volatile("cp.async.wait_group 1;" ::: "memory")
#define CP_WAIT0()  asm volatile("cp.async.wait_group 0;" ::: "memory")

__device__ __forceinline__ void ldsm4(uint32_t* r, uint32_t addr) {
    asm volatile("ldmatrix.sync.aligned.m8n8.x4.shared.b16 {%0,%1,%2,%3}, [%4];"
                 : "=r"(r[0]), "=r"(r[1]), "=r"(r[2]), "=r"(r[3]) : "r"(addr));
}

__device__ __forceinline__ void mma16816(float* c, const uint32_t* a, const uint32_t* b) {
    asm volatile(
        "mma.sync.aligned.m16n8k16.row.col.f32.f16.f16.f32 "
        "{%0,%1,%2,%3}, {%4,%5,%6,%7}, {%8,%9}, {%0,%1,%2,%3};"
        : "+f"(c[0]), "+f"(c[1]), "+f"(c[2]), "+f"(c[3])
        : "r"(a[0]), "r"(a[1]), "r"(a[2]), "r"(a[3]), "r"(b[0]), "r"(b[1]));
}

// ===========================================================================
// prep: G = concat(x,z); fill z-cols of HA/HB
// ===========================================================================
__global__ void prep_kernel(const float* __restrict__ x, const float* __restrict__ z,
                            float* __restrict__ G, float* __restrict__ HA,
                            float* __restrict__ HB) {
    int i = blockIdx.x * blockDim.x + threadIdx.x;
    const int totG = MB * GW;
    if (i < totG) {
        int b = i / GW, c = i - b * GW;
        G[i] = (c < XD) ? x[b * XD + c] : z[b * ZD + (c - XD)];
    }
    const int totZ = MB * ZD;
    if (i < totZ) {
        int b = i / ZD, c = i - b * ZD;
        float v = z[i];
        HA[b * HW + HD + c] = v;
        HB[b * HW + HD + c] = v;
    }
}

// ===========================================================================
// W split: W[e][o][kin] (fp32) -> Wh/Wl[o][e*IN+kin] (fp16 hi/lo)
// ===========================================================================
__global__ void wsplit_kernel(const float* __restrict__ W,
                              __half* __restrict__ Wh, __half* __restrict__ Wl,
                              int Nout, int IN) {
    long long idx = (long long)blockIdx.x * blockDim.x + threadIdx.x;
    long long tot4 = (long long)NE * Nout * IN / 4;
    if (idx >= tot4) return;
    long long i = idx * 4;
    int e = (int)(i / ((long long)Nout * IN));
    long long rem = i - (long long)e * Nout * IN;
    int o = (int)(rem / IN);
    int kin = (int)(rem - (long long)o * IN);
    float4 v = *reinterpret_cast<const float4*>(W + i);
    long long d = (long long)o * ((long long)NE * IN) + e * IN + kin;
    float a[4] = {v.x, v.y, v.z, v.w};
    unsigned short h[4], l[4];
#pragma unroll
    for (int j = 0; j < 4; j++) {
        __half hh = __float2half_rn(a[j]);
        float r = a[j] - __half2float(hh);
        __half ll = __float2half_rn(r);
        h[j] = __half_as_ushort(hh);
        l[j] = __half_as_ushort(ll);
    }
    uint2 hp, lp;
    hp.x = ((uint32_t)h[1] << 16) | h[0]; hp.y = ((uint32_t)h[3] << 16) | h[2];
    lp.x = ((uint32_t)l[1] << 16) | l[0]; lp.y = ((uint32_t)l[3] << 16) | l[2];
    *reinterpret_cast<uint2*>(Wh + d) = hp;
    *reinterpret_cast<uint2*>(Wl + d) = lp;
}

// ===========================================================================
// A split: A[m][kin] (fp32, row stride lda) * bc[m][e] -> Ah/Al[m][e*IN+kin]
// one thread = 8 contiguous K' elements (one 16B hi + one 16B lo store)
// ===========================================================================
__global__ void asplit_kernel(const float* __restrict__ A, int lda, int IN,
                              const float* __restrict__ bc,
                              __half* __restrict__ Ah, __half* __restrict__ Al,
                              int Kp) {
    long long g = (long long)blockIdx.x * blockDim.x + threadIdx.x;
    long long tot = (long long)MB * Kp / 8;
    if (g >= tot) return;
    int segs = Kp >> 3;
    int m = (int)(g / segs);
    int kp = (int)(g - (long long)m * segs) << 3;
    int e = kp / IN;
    int kin = kp - e * IN;
    float sc = __ldg(bc + m * NE + e);
    const float* src = A + (size_t)m * lda + kin;
    float4 v0 = *reinterpret_cast<const float4*>(src);
    float4 v1 = *reinterpret_cast<const float4*>(src + 4);
    float a[8] = {v0.x, v0.y, v0.z, v0.w, v1.x, v1.y, v1.z, v1.w};
    uint32_t hp[4], lp[4];
#pragma unroll
    for (int j = 0; j < 4; j++) {
        float x0 = a[2 * j] * sc, x1 = a[2 * j + 1] * sc;
        __half h0 = __float2half_rn(x0);
        __half h1 = __float2half_rn(x1);
        __half l0 = __float2half_rn(x0 - __half2float(h0));
        __half l1 = __float2half_rn(x1 - __half2float(h1));
        hp[j] = ((uint32_t)__half_as_ushort(h1) << 16) | __half_as_ushort(h0);
        lp[j] = ((uint32_t)__half_as_ushort(l1) << 16) | __half_as_ushort(l0);
    }
    *reinterpret_cast<uint4*>(Ah + (size_t)m * Kp + kp) = make_uint4(hp[0], hp[1], hp[2], hp[3]);
    *reinterpret_cast<uint4*>(Al + (size_t)m * Kp + kp) = make_uint4(lp[0], lp[1], lp[2], lp[3]);
}

// ===========================================================================
// HMMA GEMM: C[BM x BN tile] = act( A' @ W^T + blended bias )
// BM=256, BN=128, BK=64, 512 threads (16 warps: 4(M) x 4(N), warp 64x32).
// smem: SW128-swizzled 128B rows; cp.async double buffer.
// ===========================================================================
#define BM 256
#define BN 128
#define NTHREADS 512

#define SA_OFF    0         // 2 stages x (hi 32768 + lo 32768) = 131072
#define SW_OFF    131072    // 2 stages x (hi 16384 + lo 16384) = 65536
#define SBC_OFF   196608    // 256*8*4 = 8192
#define SBIAS_OFF 204800    // 8*128*4 = 4096
#define STOTAL    208896

__device__ __forceinline__ void load_chunk(
    const __half* __restrict__ Ah, const __half* __restrict__ Al,
    const __half* __restrict__ Wh, const __half* __restrict__ Wl,
    int Kp, int mBase, int nBase, uint32_t aDst, uint32_t wDst, int kc, int tid)
{
#pragma unroll
    for (int i = 0; i < 8; i++) {
        int lin = tid + i * 512;
        int hl = lin >> 11;
        int wi = lin & 2047;
        int r = wi >> 3, ks = wi & 7;
        const __half* src = (hl ? Al : Ah) + (size_t)(mBase + r) * Kp + kc + ks * 8;
        uint32_t dst = aDst + (uint32_t)hl * 32768u + (uint32_t)r * 128u +
                       (((uint32_t)ks * 16u) ^ (((uint32_t)r & 7u) << 4));
        cp_async16(dst, src);
    }
#pragma unroll
    for (int i = 0; i < 4; i++) {
        int lin = tid + i * 512;
        int hl = lin >> 10;
        int wi = lin & 1023;
        int o = wi >> 3, ks = wi & 7;
        const __half* src = (hl ? Wl : Wh) + (size_t)(nBase + o) * Kp + kc + ks * 8;
        uint32_t dst = wDst + (uint32_t)hl * 16384u + (uint32_t)o * 128u +
                       (((uint32_t)ks * 16u) ^ (((uint32_t)o & 7u) << 4));
        cp_async16(dst, src);
    }
}

__global__ __launch_bounds__(NTHREADS, 1)
void moe_hmma_gemm(const __half* __restrict__ Ah, const __half* __restrict__ Al,
                   const __half* __restrict__ Wh, const __half* __restrict__ Wl,
                   int Kp,
                   const float* __restrict__ bias,  // [NE][Nout]
                   const float* __restrict__ bc,    // [MB][NE]
                   int Nout, float* __restrict__ C, int ldc, int applyElu)
{
    extern __shared__ char smem[];
    const uint32_t sb = smem_u32(smem);
    const int tid = threadIdx.x;
    const int lane = tid & 31;
    const int wid = tid >> 5;
    const int wm = wid & 3;       // 0..3 along M (64 rows each)
    const int wn = wid >> 2;      // 0..3 along N (32 cols each)
    const int mBase = blockIdx.y * BM;
    const int nBase = blockIdx.x * BN;
    const int NC = Kp >> 6;

    float* bcs    = reinterpret_cast<float*>(smem + SBC_OFF);   // [256][8]
    float* bias_s = reinterpret_cast<float*>(smem + SBIAS_OFF); // [8][128]
    reinterpret_cast<float4*>(bcs)[tid] =
        reinterpret_cast<const float4*>(bc + (size_t)mBase * NE)[tid];
    if (tid < 256) {
        int e = tid >> 5, cs = (tid & 31) << 2;
        reinterpret_cast<float4*>(bias_s + e * BN + cs)[0] =
            reinterpret_cast<const float4*>(bias + (size_t)e * Nout + nBase + cs)[0];
    }

    // prologue: stage chunks 0 and 1
    load_chunk(Ah, Al, Wh, Wl, Kp, mBase, nBase, sb + SA_OFF, sb + SW_OFF, 0, tid);
    CP_COMMIT();
    load_chunk(Ah, Al, Wh, Wl, Kp, mBase, nBase, sb + SA_OFF + 65536u,
               sb + SW_OFF + 32768u, 64, tid);
    CP_COMMIT();
    CP_WAIT1();
    __syncthreads();

    float acc[4][4][4];
#pragma unroll
    for (int a = 0; a < 4; a++)
#pragma unroll
        for (int b = 0; b < 4; b++)
#pragma unroll
            for (int c = 0; c < 4; c++) acc[a][b][c] = 0.f;

    // per-thread ldmatrix address pieces
    const int aRow = wm * 64 + (lane & 15);
    const uint32_t aXor = ((uint32_t)aRow & 7u) << 4;
    const uint32_t aKb = ((uint32_t)lane >> 4) << 4;
    const uint32_t aRowOff = (uint32_t)aRow * 128u;
    const int bRow = wn * 32 + (lane & 7) + (((lane >> 4) & 1) << 3);
    const uint32_t bXor = ((uint32_t)bRow & 7u) << 4;
    const uint32_t bKb = (((uint32_t)lane >> 3) & 1u) << 4;
    const uint32_t bRowOff = (uint32_t)bRow * 128u;

    for (int c = 0; c < NC; c++) {
        const int st = c & 1;
        const uint32_t aSt = sb + SA_OFF + (uint32_t)st * 65536u;
        const uint32_t wSt = sb + SW_OFF + (uint32_t)st * 32768u;

#pragma unroll
        for (int kk = 0; kk < 4; kk++) {
            const uint32_t kA = ((uint32_t)(kk * 32) + aKb) ^ aXor;
            const uint32_t kB = ((uint32_t)(kk * 32) + bKb) ^ bXor;
            uint32_t bfh[8], bfl[8], af[4][4];
#pragma unroll
            for (int g = 0; g < 2; g++) {
                ldsm4(&bfh[4 * g], wSt + bRowOff + (uint32_t)g * 2048u + kB);
                ldsm4(&bfl[4 * g], wSt + 16384u + bRowOff + (uint32_t)g * 2048u + kB);
            }
#pragma unroll
            for (int mf = 0; mf < 4; mf++)
                ldsm4(af[mf], aSt + aRowOff + (uint32_t)mf * 2048u + kA);
#pragma unroll
            for (int mf = 0; mf < 4; mf++)
#pragma unroll
                for (int nf = 0; nf < 4; nf++)
                    mma16816(acc[mf][nf], af[mf], &bfh[2 * nf]);
#pragma unroll
            for (int mf = 0; mf < 4; mf++)
#pragma unroll
                for (int nf = 0; nf < 4; nf++)
                    mma16816(acc[mf][nf], af[mf], &bfl[2 * nf]);
#pragma unroll
            for (int mf = 0; mf < 4; mf++)
                ldsm4(af[mf], aSt + 32768u + aRowOff + (uint32_t)mf * 2048u + kA);
#pragma unroll
            for (int mf = 0; mf < 4; mf++)
#pragma unroll
                for (int nf = 0; nf < 4; nf++)
                    mma16816(acc[mf][nf], af[mf], &bfh[2 * nf]);
        }

        __syncthreads();
        if (c + 2 < NC) {
            load_chunk(Ah, Al, Wh, Wl, Kp, mBase, nBase, aSt, wSt, (c + 2) * 64, tid);
            CP_COMMIT();
            CP_WAIT1();
        } else {
            CP_WAIT0();
        }
        __syncthreads();
    }

    // ---- epilogue: blended bias + ELU, direct float2 stores ----
#pragma unroll
    for (int mf = 0; mf < 4; mf++) {
        const int r0 = wm * 64 + mf * 16 + (lane >> 2);
        const int r1 = r0 + 8;
        float bcv0[NE], bcv1[NE];
#pragma unroll
        for (int e = 0; e < NE; e++) { bcv0[e] = bcs[r0 * 8 + e]; bcv1[e] = bcs[r1 * 8 + e]; }
#pragma unroll
        for (int nf = 0; nf < 4; nf++) {
            const int cl = wn * 32 + nf * 8 + ((lane & 3) << 1);
            float bb00 = 0.f, bb01 = 0.f, bb10 = 0.f, bb11 = 0.f;
#pragma unroll
            for (int e = 0; e < NE; e++) {
                float be0 = bias_s[e * BN + cl], be1 = bias_s[e * BN + cl + 1];
                bb00 = fmaf(bcv0[e], be0, bb00);
                bb01 = fmaf(bcv0[e], be1, bb01);
                bb10 = fmaf(bcv1[e], be0, bb10);
                bb11 = fmaf(bcv1[e], be1, bb11);
            }
            float v00 = acc[mf][nf][0] + bb00;
            float v01 = acc[mf][nf][1] + bb01;
            float v10 = acc[mf][nf][2] + bb10;
            float v11 = acc[mf][nf][3] + bb11;
            if (applyElu) {
                v00 = (v00 > 0.f) ? v00 : expm1f(v00);
                v01 = (v01 > 0.f) ? v01 : expm1f(v01);
                v10 = (v10 > 0.f) ? v10 : expm1f(v10);
                v11 = (v11 > 0.f) ? v11 : expm1f(v11);
            }
            const int gc = nBase + cl;
            *reinterpret_cast<float2*>(C + (size_t)(mBase + r0) * ldc + gc) =
                make_float2(v00, v01);
            *reinterpret_cast<float2*>(C + (size_t)(mBase + r1) * ldc + gc) =
                make_float2(v10, v11);
        }
    }
}

// ===========================================================================
// gate GEMM: BM=32, BN=128(=Nout), BK=16, elu. grid = 4096/32 = 128
// ===========================================================================
__global__ __launch_bounds__(256, 4)
void gate_gemm_kernel(const float* __restrict__ A, int IN,
                      const float* __restrict__ W,   // [128][IN]
                      const float* __restrict__ bias,
                      float* __restrict__ C) {
    __shared__ float As[16][32];
    __shared__ float Bs[16][128];
    const int tid = threadIdx.x;
    const int tx = tid & 15, ty = tid >> 4;
    const int mBase = blockIdx.x * 32;

    float acc[2][8];
#pragma unroll
    for (int i = 0; i < 2; i++)
#pragma unroll
        for (int j = 0; j < 8; j++) acc[i][j] = 0.f;

    const int r2 = tid >> 2;
    const int vec = (tid & 3) << 2;

    for (int k0 = 0; k0 < IN; k0 += 16) {
        if (tid < 128) {
            int r = tid >> 2;
            float4 v = *reinterpret_cast<const float4*>(A + (size_t)(mBase + r) * IN + k0 + vec);
            As[vec + 0][r] = v.x; As[vec + 1][r] = v.y;
            As[vec + 2][r] = v.z; As[vec + 3][r] = v.w;
        }
#pragma unroll
        for (int rr = 0; rr < 2; rr++) {
            int o = r2 + rr * 64;
            float4 v = *reinterpret_cast<const float4*>(W + (size_t)o * IN + k0 + vec);
            Bs[vec + 0][o] = v.x; Bs[vec + 1][o] = v.y;
            Bs[vec + 2][o] = v.z; Bs[vec + 3][o] = v.w;
        }
        __syncthreads();
#pragma unroll
        for (int k = 0; k < 16; k++) {
            float a0 = As[k][ty * 2], a1 = As[k][ty * 2 + 1];
            float4 b0 = *reinterpret_cast<const float4*>(&Bs[k][tx * 8]);
            float4 b1 = *reinterpret_cast<const float4*>(&Bs[k][tx * 8 + 4]);
            float bv[8] = {b0.x, b0.y, b0.z, b0.w, b1.x, b1.y, b1.z, b1.w};
#pragma unroll
            for (int j = 0; j < 8; j++) {
                acc[0][j] = fmaf(a0, bv[j], acc[0][j]);
                acc[1][j] = fmaf(a1, bv[j], acc[1][j]);
            }
        }
        __syncthreads();
    }
#pragma unroll
    for (int i = 0; i < 2; i++) {
        int grow = mBase + ty * 2 + i;
#pragma unroll
        for (int j = 0; j < 8; j++) {
            int gcol = tx * 8 + j;
            float v = acc[i][j] + __ldg(bias + gcol);
            v = (v > 0.f) ? v : expm1f(v);
            C[(size_t)grow * GHD + gcol] = v;
        }
    }
}

// ===========================================================================
// gate3 + softmax (one warp per row)
// ===========================================================================
__global__ void gate3_softmax_kernel(const float* __restrict__ H2,
                                     const float* __restrict__ Wg3,
                                     const float* __restrict__ bg3,
                                     float* __restrict__ BC) {
    int warp = (blockIdx.x * blockDim.x + threadIdx.x) >> 5;
    int lane = threadIdx.x & 31;
    if (warp >= MB) return;
    const float* h = H2 + (size_t)warp * GHD;
    float hv[4];
#pragma unroll
    for (int t = 0; t < 4; t++) hv[t] = h[lane + 32 * t];
    float s[NE];
#pragma unroll
    for (int e = 0; e < NE; e++) {
        float p = 0.f;
#pragma unroll
        for (int t = 0; t < 4; t++)
            p = fmaf(hv[t], __ldg(Wg3 + e * GHD + lane + 32 * t), p);
#pragma unroll
        for (int off = 16; off > 0; off >>= 1) p += __shfl_xor_sync(0xFFFFFFFFu, p, off);
        s[e] = p + __ldg(bg3 + e);
    }
    float mx = s[0];
#pragma unroll
    for (int e = 1; e < NE; e++) mx = fmaxf(mx, s[e]);
    float sum = 0.f;
#pragma unroll
    for (int e = 0; e < NE; e++) { s[e] = expf(s[e] - mx); sum += s[e]; }
    float inv = 1.f / sum;
    if (lane < NE) BC[(size_t)warp * NE + lane] = s[lane] * inv;
}

// ===========================================================================
extern "C" void kernel_launch(void* const* d_in, const int* in_sizes, int n_in,
                              void* d_out, int out_size) {
    const float* x   = (const float*)d_in[0];
    const float* z   = (const float*)d_in[1];
    const float* Wg1 = (const float*)d_in[2];
    const float* bg1 = (const float*)d_in[3];
    const float* Wg2 = (const float*)d_in[4];
    const float* bg2 = (const float*)d_in[5];
    const float* Wg3 = (const float*)d_in[6];
    const float* bg3 = (const float*)d_in[7];
    const float* W0  = (const float*)d_in[8];
    const float* b0  = (const float*)d_in[9];
    const float* W1  = (const float*)d_in[10];
    const float* b1  = (const float*)d_in[11];
    const float* W2  = (const float*)d_in[12];
    const float* b2  = (const float*)d_in[13];
    const float* W3  = (const float*)d_in[14];
    const float* b3  = (const float*)d_in[15];
    float* out = (float*)d_out;

    float *G, *H1, *H2, *BC, *HA, *HB;
    __half *Ah, *Al, *W0h, *W0l, *W1h, *W1l, *W2h, *W2l, *W3h, *W3l;
    cudaGetSymbolAddress((void**)&G,  g_G);
    cudaGetSymbolAddress((void**)&H1, g_H1);
    cudaGetSymbolAddress((void**)&H2, g_H2);
    cudaGetSymbolAddress((void**)&BC, g_BC);
    cudaGetSymbolAddress((void**)&HA, g_HA);
    cudaGetSymbolAddress((void**)&HB, g_HB);
    cudaGetSymbolAddress((void**)&Ah, g_Ah);
    cudaGetSymbolAddress((void**)&Al, g_Al);
    cudaGetSymbolAddress((void**)&W0h, g_W0h);
    cudaGetSymbolAddress((void**)&W0l, g_W0l);
    cudaGetSymbolAddress((void**)&W1h, g_W1h);
    cudaGetSymbolAddress((void**)&W1l, g_W1l);
    cudaGetSymbolAddress((void**)&W2h, g_W2h);
    cudaGetSymbolAddress((void**)&W2l, g_W2l);
    cudaGetSymbolAddress((void**)&W3h, g_W3h);
    cudaGetSymbolAddress((void**)&W3l, g_W3l);

    cudaFuncSetAttribute(moe_hmma_gemm, cudaFuncAttributeMaxDynamicSharedMemorySize, STOTAL);

    // prep
    prep_kernel<<<(MB * GW + 255) / 256, 256>>>(x, z, G, HA, HB);

    // weight splits
    {
        long long t0 = (long long)NE * HD * GW / 4;
        wsplit_kernel<<<(unsigned)((t0 + 255) / 256), 256>>>(W0, W0h, W0l, HD, GW);
        long long t1 = (long long)NE * HD * HW / 4;
        wsplit_kernel<<<(unsigned)((t1 + 255) / 256), 256>>>(W1, W1h, W1l, HD, HW);
        wsplit_kernel<<<(unsigned)((t1 + 255) / 256), 256>>>(W2, W2h, W2l, HD, HW);
        long long t3 = (long long)NE * OD * HD / 4;
        wsplit_kernel<<<(unsigned)((t3 + 255) / 256), 256>>>(W3, W3h, W3l, OD, HD);
    }

    // gate network
    gate_gemm_kernel<<<MB / 32, 256>>>(G, GW, Wg1, bg1, H1);
    gate_gemm_kernel<<<MB / 32, 256>>>(H1, GHD, Wg2, bg2, H2);
    gate3_softmax_kernel<<<(MB * 32 + 255) / 256, 256>>>(H2, Wg3, bg3, BC);

    // layer 0: inp = G [MB,864], Kp = 6912 -> HA[:, :1024], elu
    {
        long long tot = (long long)MB * KP0 / 8;
        asplit_kernel<<<(unsigned)((tot + 255) / 256), 256>>>(G, GW, GW, BC, Ah, Al, KP0);
        moe_hmma_gemm<<<dim3(HD / BN, MB / BM), NTHREADS, STOTAL>>>(
            Ah, Al, W0h, W0l, KP0, b0, BC, HD, HA, HW, 1);
    }
    // layer 1: inp = HA [MB,1088], Kp = 8704 -> HB[:, :1024], elu
    {
        long long tot = (long long)MB * KP1 / 8;
        asplit_kernel<<<(unsigned)((tot + 255) / 256), 256>>>(HA, HW, HW, BC, Ah, Al, KP1);
        moe_hmma_gemm<<<dim3(HD / BN, MB / BM), NTHREADS, STOTAL>>>(
            Ah, Al, W1h, W1l, KP1, b1, BC, HD, HB, HW, 1);
    }
    // layer 2: inp = HB -> HA[:, :1024], elu
    {
        long long tot = (long long)MB * KP1 / 8;
        asplit_kernel<<<(unsigned)((tot + 255) / 256), 256>>>(HB, HW, HW, BC, Ah, Al, KP1);
        moe_hmma_gemm<<<dim3(HD / BN, MB / BM), NTHREADS, STOTAL>>>(
            Ah, Al, W2h, W2l, KP1, b2, BC, HD, HA, HW, 1);
    }
    // layer 3: inp = HA cols 0..1023 (IN=1024, lda=1088), Kp = 8192 -> out, no act
    {
        long long tot = (long long)MB * KP3 / 8;
        asplit_kernel<<<(unsigned)((tot + 255) / 256), 256>>>(HA, HW, HD, BC, Ah, Al, KP3);
        moe_hmma_gemm<<<dim3(OD / BN, MB / BM), NTHREADS, STOTAL>>>(
            Ah, Al, W3h, W3l, KP3, b3, BC, OD, out, OD, 0);
    }
}

// round 5
// speedup vs baseline: 3.2237x; 1.0075x over previous
#include <cuda_runtime.h>
#include <cuda_fp16.h>
#include <math.h>
#include <stdint.h>

// ===========================================================================
// MVAEdecoder via HMMA (mma.sync m16n8k16), 3-term fp16 split:
//   a = ah+al, w = wh+wl;  D = [ah*wh]_f32acc + [ah*wl + al*wh]_f16acc
// blend(bc,inp,W,b) => GEMM with K' = E*IN; A'[m,e*IN+k] = bc[m,e]*inp[m,k].
// ===========================================================================

#define MB 4096
#define XD 800
#define ZD 64
#define HD 1024
#define OD 768
#define GHD 128
#define NE 8
#define GW (XD + ZD)   // 864
#define HW (HD + ZD)   // 1088

#define KP0 (NE * GW)  // 6912
#define KP1 (NE * HW)  // 8704
#define KP3 (NE * HD)  // 8192

// ---------------- static device scratch ----------------
__device__ __align__(128) float g_G [MB * GW];
__device__ __align__(128) float g_H1[MB * GHD];
__device__ __align__(128) float g_H2[MB * GHD];
__device__ __align__(128) float g_BC[MB * NE];
__device__ __align__(128) float g_HA[MB * HW];
__device__ __align__(128) float g_HB[MB * HW];

// pre-split A' (bc-scaled, expert-replicated), fp16 hi/lo, max K' = 8704
__device__ __align__(128) __half g_Ah[MB * KP1];
__device__ __align__(128) __half g_Al[MB * KP1];

// fp16 hi/lo weight copies, layout [Nout][K'=NE*IN]
__device__ __align__(128) __half g_W0h[HD * KP0];
__device__ __align__(128) __half g_W0l[HD * KP0];
__device__ __align__(128) __half g_W1h[HD * KP1];
__device__ __align__(128) __half g_W1l[HD * KP1];
__device__ __align__(128) __half g_W2h[HD * KP1];
__device__ __align__(128) __half g_W2l[HD * KP1];
__device__ __align__(128) __half g_W3h[OD * KP3];
__device__ __align__(128) __half g_W3l[OD * KP3];

// ---------------- PTX helpers ----------------
__device__ __forceinline__ uint32_t smem_u32(const void* p) {
    uint32_t a;
    asm("{ .reg .u64 t; cvta.to.shared.u64 t, %1; cvt.u32.u64 %0, t; }" : "=r"(a) : "l"(p));
    return a;
}

__device__ __forceinline__ void cp_async16(uint32_t dst, const void* src) {
    asm volatile("cp.async.cg.shared.global [%0], [%1], 16;" :: "r"(dst), "l"(src) : "memory");
}
#define CP_COMMIT() asm volatile("cp.async.commit_group;" ::: "memory")
#define CP_WAIT1()  asm volatile("cp.async.wait_group 1;" ::: "memory")
#define CP_WAIT0()  asm volatile("cp.async.wait_group 0;" ::: "memory")

__device__ __forceinline__ void ldsm4(uint32_t* r, uint32_t addr) {
    asm volatile("ldmatrix.sync.aligned.m8n8.x4.shared.b16 {%0,%1,%2,%3}, [%4];"
                 : "=r"(r[0]), "=r"(r[1]), "=r"(r[2]), "=r"(r[3]) : "r"(addr));
}

__device__ __forceinline__ void mma16816_f32(float* c, const uint32_t* a, const uint32_t* b) {
    asm volatile(
        "mma.sync.aligned.m16n8k16.row.col.f32.f16.f16.f32 "
        "{%0,%1,%2,%3}, {%4,%5,%6,%7}, {%8,%9}, {%0,%1,%2,%3};"
        : "+f"(c[0]), "+f"(c[1]), "+f"(c[2]), "+f"(c[3])
        : "r"(a[0]), "r"(a[1]), "r"(a[2]), "r"(a[3]), "r"(b[0]), "r"(b[1]));
}

__device__ __forceinline__ void mma16816_f16(uint32_t* c, const uint32_t* a, const uint32_t* b) {
    asm volatile(
        "mma.sync.aligned.m16n8k16.row.col.f16.f16.f16.f16 "
        "{%0,%1}, {%2,%3,%4,%5}, {%6,%7}, {%0,%1};"
        : "+r"(c[0]), "+r"(c[1])
        : "r"(a[0]), "r"(a[1]), "r"(a[2]), "r"(a[3]), "r"(b[0]), "r"(b[1]));
}

// ===========================================================================
// prep: G = concat(x,z); fill z-cols of HA/HB
// ===========================================================================
__global__ void prep_kernel(const float* __restrict__ x, const float* __restrict__ z,
                            float* __restrict__ G, float* __restrict__ HA,
                            float* __restrict__ HB) {
    int i = blockIdx.x * blockDim.x + threadIdx.x;
    const int totG = MB * GW;
    if (i < totG) {
        int b = i / GW, c = i - b * GW;
        G[i] = (c < XD) ? x[b * XD + c] : z[b * ZD + (c - XD)];
    }
    const int totZ = MB * ZD;
    if (i < totZ) {
        int b = i / ZD, c = i - b * ZD;
        float v = z[i];
        HA[b * HW + HD + c] = v;
        HB[b * HW + HD + c] = v;
    }
}

// ===========================================================================
// W split: W[e][o][kin] (fp32) -> Wh/Wl[o][e*IN+kin] (fp16 hi/lo)
// ===========================================================================
__global__ void wsplit_kernel(const float* __restrict__ W,
                              __half* __restrict__ Wh, __half* __restrict__ Wl,
                              int Nout, int IN) {
    long long idx = (long long)blockIdx.x * blockDim.x + threadIdx.x;
    long long tot4 = (long long)NE * Nout * IN / 4;
    if (idx >= tot4) return;
    long long i = idx * 4;
    int e = (int)(i / ((long long)Nout * IN));
    long long rem = i - (long long)e * Nout * IN;
    int o = (int)(rem / IN);
    int kin = (int)(rem - (long long)o * IN);
    float4 v = *reinterpret_cast<const float4*>(W + i);
    long long d = (long long)o * ((long long)NE * IN) + e * IN + kin;
    float a[4] = {v.x, v.y, v.z, v.w};
    unsigned short h[4], l[4];
#pragma unroll
    for (int j = 0; j < 4; j++) {
        __half hh = __float2half_rn(a[j]);
        float r = a[j] - __half2float(hh);
        __half ll = __float2half_rn(r);
        h[j] = __half_as_ushort(hh);
        l[j] = __half_as_ushort(ll);
    }
    uint2 hp, lp;
    hp.x = ((uint32_t)h[1] << 16) | h[0]; hp.y = ((uint32_t)h[3] << 16) | h[2];
    lp.x = ((uint32_t)l[1] << 16) | l[0]; lp.y = ((uint32_t)l[3] << 16) | l[2];
    *reinterpret_cast<uint2*>(Wh + d) = hp;
    *reinterpret_cast<uint2*>(Wl + d) = lp;
}

// ===========================================================================
// A split: A[m][kin] (fp32, row stride lda) * bc[m][e] -> Ah/Al[m][e*IN+kin]
// ===========================================================================
__global__ void asplit_kernel(const float* __restrict__ A, int lda, int IN,
                              const float* __restrict__ bc,
                              __half* __restrict__ Ah, __half* __restrict__ Al,
                              int Kp) {
    long long g = (long long)blockIdx.x * blockDim.x + threadIdx.x;
    long long tot = (long long)MB * Kp / 8;
    if (g >= tot) return;
    int segs = Kp >> 3;
    int m = (int)(g / segs);
    int kp = (int)(g - (long long)m * segs) << 3;
    int e = kp / IN;
    int kin = kp - e * IN;
    float sc = __ldg(bc + m * NE + e);
    const float* src = A + (size_t)m * lda + kin;
    float4 v0 = *reinterpret_cast<const float4*>(src);
    float4 v1 = *reinterpret_cast<const float4*>(src + 4);
    float a[8] = {v0.x, v0.y, v0.z, v0.w, v1.x, v1.y, v1.z, v1.w};
    uint32_t hp[4], lp[4];
#pragma unroll
    for (int j = 0; j < 4; j++) {
        float x0 = a[2 * j] * sc, x1 = a[2 * j + 1] * sc;
        __half h0 = __float2half_rn(x0);
        __half h1 = __float2half_rn(x1);
        __half l0 = __float2half_rn(x0 - __half2float(h0));
        __half l1 = __float2half_rn(x1 - __half2float(h1));
        hp[j] = ((uint32_t)__half_as_ushort(h1) << 16) | __half_as_ushort(h0);
        lp[j] = ((uint32_t)__half_as_ushort(l1) << 16) | __half_as_ushort(l0);
    }
    *reinterpret_cast<uint4*>(Ah + (size_t)m * Kp + kp) = make_uint4(hp[0], hp[1], hp[2], hp[3]);
    *reinterpret_cast<uint4*>(Al + (size_t)m * Kp + kp) = make_uint4(lp[0], lp[1], lp[2], lp[3]);
}

// ===========================================================================
// HMMA GEMM: BM=128, BN=128, BK=64, 256 threads (8 warps: 2(M) x 4(N),
// warp tile 64x32). Main term fp32-acc; two correction terms share fp16-acc.
// ===========================================================================
#define BM 128
#define BN 128
#define NTHREADS 256

#define SA_OFF    0         // 2 stages x (hi 16384 + lo 16384) = 65536
#define SW_OFF    65536     // 2 stages x (hi 16384 + lo 16384) = 65536
#define SBC_OFF   131072    // 128*8*4 = 4096
#define SBIAS_OFF 135168    // 8*128*4 = 4096
#define STOTAL    139264

__device__ __forceinline__ void load_chunk(
    const __half* __restrict__ Ah, const __half* __restrict__ Al,
    const __half* __restrict__ Wh, const __half* __restrict__ Wl,
    int Kp, int mBase, int nBase, uint32_t aDst, uint32_t wDst, int kc, int tid)
{
#pragma unroll
    for (int i = 0; i < 8; i++) {
        int lin = tid + i * 256;
        int hl = lin >> 10;
        int wi = lin & 1023;
        int r = wi >> 3, ks = wi & 7;
        const __half* src = (hl ? Al : Ah) + (size_t)(mBase + r) * Kp + kc + ks * 8;
        uint32_t dst = aDst + (uint32_t)hl * 16384u + (uint32_t)r * 128u +
                       (((uint32_t)ks * 16u) ^ (((uint32_t)r & 7u) << 4));
        cp_async16(dst, src);
    }
#pragma unroll
    for (int i = 0; i < 8; i++) {
        int lin = tid + i * 256;
        int hl = lin >> 10;
        int wi = lin & 1023;
        int o = wi >> 3, ks = wi & 7;
        const __half* src = (hl ? Wl : Wh) + (size_t)(nBase + o) * Kp + kc + ks * 8;
        uint32_t dst = wDst + (uint32_t)hl * 16384u + (uint32_t)o * 128u +
                       (((uint32_t)ks * 16u) ^ (((uint32_t)o & 7u) << 4));
        cp_async16(dst, src);
    }
}

__global__ __launch_bounds__(NTHREADS, 1)
void moe_hmma_gemm(const __half* __restrict__ Ah, const __half* __restrict__ Al,
                   const __half* __restrict__ Wh, const __half* __restrict__ Wl,
                   int Kp,
                   const float* __restrict__ bias,  // [NE][Nout]
                   const float* __restrict__ bc,    // [MB][NE]
                   int Nout, float* __restrict__ C, int ldc, int applyElu)
{
    extern __shared__ char smem[];
    const uint32_t sb = smem_u32(smem);
    const int tid = threadIdx.x;
    const int lane = tid & 31;
    const int wid = tid >> 5;
    const int wm = wid & 1;       // 0..1 along M (64 rows each)
    const int wn = wid >> 1;      // 0..3 along N (32 cols each)
    const int mBase = blockIdx.y * BM;
    const int nBase = blockIdx.x * BN;
    const int NC = Kp >> 6;

    float* bcs    = reinterpret_cast<float*>(smem + SBC_OFF);   // [128][8]
    float* bias_s = reinterpret_cast<float*>(smem + SBIAS_OFF); // [8][128]
    reinterpret_cast<float4*>(bcs)[tid] =
        reinterpret_cast<const float4*>(bc + (size_t)mBase * NE)[tid];
    {
        int e = tid >> 5, cs = (tid & 31) << 2;
        reinterpret_cast<float4*>(bias_s + e * BN + cs)[0] =
            reinterpret_cast<const float4*>(bias + (size_t)e * Nout + nBase + cs)[0];
    }

    // prologue: stage chunks 0 and 1
    load_chunk(Ah, Al, Wh, Wl, Kp, mBase, nBase, sb + SA_OFF, sb + SW_OFF, 0, tid);
    CP_COMMIT();
    load_chunk(Ah, Al, Wh, Wl, Kp, mBase, nBase, sb + SA_OFF + 32768u,
               sb + SW_OFF + 32768u, 64, tid);
    CP_COMMIT();
    CP_WAIT1();
    __syncthreads();

    float acc[4][4][4];
    uint32_t accc[4][4][2];
#pragma unroll
    for (int a = 0; a < 4; a++)
#pragma unroll
        for (int b = 0; b < 4; b++) {
#pragma unroll
            for (int q = 0; q < 4; q++) acc[a][b][q] = 0.f;
            accc[a][b][0] = 0u; accc[a][b][1] = 0u;
        }

    // per-thread ldmatrix address pieces
    const int aRow = wm * 64 + (lane & 15);
    const uint32_t aXor = ((uint32_t)aRow & 7u) << 4;
    const uint32_t aKb = ((uint32_t)lane >> 4) << 4;
    const uint32_t aRowOff = (uint32_t)aRow * 128u;
    const int bRow = wn * 32 + (lane & 7) + (((lane >> 4) & 1) << 3);
    const uint32_t bXor = ((uint32_t)bRow & 7u) << 4;
    const uint32_t bKb = (((uint32_t)lane >> 3) & 1u) << 4;
    const uint32_t bRowOff = (uint32_t)bRow * 128u;

    for (int c = 0; c < NC; c++) {
        const int st = c & 1;
        const uint32_t aSt = sb + SA_OFF + (uint32_t)st * 32768u;
        const uint32_t wSt = sb + SW_OFF + (uint32_t)st * 32768u;

#pragma unroll
        for (int kk = 0; kk < 4; kk++) {
            const uint32_t kA = ((uint32_t)(kk * 32) + aKb) ^ aXor;
            const uint32_t kB = ((uint32_t)(kk * 32) + bKb) ^ bXor;
            uint32_t bfh[8], bfl[8], af[4][4];
#pragma unroll
            for (int g = 0; g < 2; g++) {
                ldsm4(&bfh[4 * g], wSt + bRowOff + (uint32_t)g * 2048u + kB);
                ldsm4(&bfl[4 * g], wSt + 16384u + bRowOff + (uint32_t)g * 2048u + kB);
            }
            // ah fragments: main term (fp32 acc) + ah*wl correction (fp16 acc)
#pragma unroll
            for (int mf = 0; mf < 4; mf++)
                ldsm4(af[mf], aSt + aRowOff + (uint32_t)mf * 2048u + kA);
#pragma unroll
            for (int mf = 0; mf < 4; mf++)
#pragma unroll
                for (int nf = 0; nf < 4; nf++)
                    mma16816_f32(acc[mf][nf], af[mf], &bfh[2 * nf]);
#pragma unroll
            for (int mf = 0; mf < 4; mf++)
#pragma unroll
                for (int nf = 0; nf < 4; nf++)
                    mma16816_f16(accc[mf][nf], af[mf], &bfl[2 * nf]);
            // al fragments: al*wh correction (fp16 acc)
#pragma unroll
            for (int mf = 0; mf < 4; mf++)
                ldsm4(af[mf], aSt + 16384u + aRowOff + (uint32_t)mf * 2048u + kA);
#pragma unroll
            for (int mf = 0; mf < 4; mf++)
#pragma unroll
                for (int nf = 0; nf < 4; nf++)
                    mma16816_f16(accc[mf][nf], af[mf], &bfh[2 * nf]);
        }

        __syncthreads();
        if (c + 2 < NC) {
            load_chunk(Ah, Al, Wh, Wl, Kp, mBase, nBase, aSt, wSt, (c + 2) * 64, tid);
            CP_COMMIT();
            CP_WAIT1();
        } else {
            CP_WAIT0();
        }
        __syncthreads();
    }

    // ---- epilogue: main + fp16 corrections + blended bias + ELU ----
#pragma unroll
    for (int mf = 0; mf < 4; mf++) {
        const int r0 = wm * 64 + mf * 16 + (lane >> 2);
        const int r1 = r0 + 8;
        float bcv0[NE], bcv1[NE];
#pragma unroll
        for (int e = 0; e < NE; e++) { bcv0[e] = bcs[r0 * 8 + e]; bcv1[e] = bcs[r1 * 8 + e]; }
#pragma unroll
        for (int nf = 0; nf < 4; nf++) {
            const int cl = wn * 32 + nf * 8 + ((lane & 3) << 1);
            float bb00 = 0.f, bb01 = 0.f, bb10 = 0.f, bb11 = 0.f;
#pragma unroll
            for (int e = 0; e < NE; e++) {
                float be0 = bias_s[e * BN + cl], be1 = bias_s[e * BN + cl + 1];
                bb00 = fmaf(bcv0[e], be0, bb00);
                bb01 = fmaf(bcv0[e], be1, bb01);
                bb10 = fmaf(bcv1[e], be0, bb10);
                bb11 = fmaf(bcv1[e], be1, bb11);
            }
            __half2 c01 = *reinterpret_cast<__half2*>(&accc[mf][nf][0]);
            __half2 c23 = *reinterpret_cast<__half2*>(&accc[mf][nf][1]);
            float v00 = acc[mf][nf][0] + __low2float(c01) + bb00;
            float v01 = acc[mf][nf][1] + __high2float(c01) + bb01;
            float v10 = acc[mf][nf][2] + __low2float(c23) + bb10;
            float v11 = acc[mf][nf][3] + __high2float(c23) + bb11;
            if (applyElu) {
                v00 = (v00 > 0.f) ? v00 : expm1f(v00);
                v01 = (v01 > 0.f) ? v01 : expm1f(v01);
                v10 = (v10 > 0.f) ? v10 : expm1f(v10);
                v11 = (v11 > 0.f) ? v11 : expm1f(v11);
            }
            const int gc = nBase + cl;
            *reinterpret_cast<float2*>(C + (size_t)(mBase + r0) * ldc + gc) =
                make_float2(v00, v01);
            *reinterpret_cast<float2*>(C + (size_t)(mBase + r1) * ldc + gc) =
                make_float2(v10, v11);
        }
    }
}

// ===========================================================================
// gate GEMM: BM=32, BN=128(=Nout), BK=16, elu. grid = 4096/32 = 128
// ===========================================================================
__global__ __launch_bounds__(256, 4)
void gate_gemm_kernel(const float* __restrict__ A, int IN,
                      const float* __restrict__ W,   // [128][IN]
                      const float* __restrict__ bias,
                      float* __restrict__ C) {
    __shared__ float As[16][32];
    __shared__ float Bs[16][128];
    const int tid = threadIdx.x;
    const int tx = tid & 15, ty = tid >> 4;
    const int mBase = blockIdx.x * 32;

    float acc[2][8];
#pragma unroll
    for (int i = 0; i < 2; i++)
#pragma unroll
        for (int j = 0; j < 8; j++) acc[i][j] = 0.f;

    const int r2 = tid >> 2;
    const int vec = (tid & 3) << 2;

    for (int k0 = 0; k0 < IN; k0 += 16) {
        if (tid < 128) {
            int r = tid >> 2;
            float4 v = *reinterpret_cast<const float4*>(A + (size_t)(mBase + r) * IN + k0 + vec);
            As[vec + 0][r] = v.x; As[vec + 1][r] = v.y;
            As[vec + 2][r] = v.z; As[vec + 3][r] = v.w;
        }
#pragma unroll
        for (int rr = 0; rr < 2; rr++) {
            int o = r2 + rr * 64;
            float4 v = *reinterpret_cast<const float4*>(W + (size_t)o * IN + k0 + vec);
            Bs[vec + 0][o] = v.x; Bs[vec + 1][o] = v.y;
            Bs[vec + 2][o] = v.z; Bs[vec + 3][o] = v.w;
        }
        __syncthreads();
#pragma unroll
        for (int k = 0; k < 16; k++) {
            float a0 = As[k][ty * 2], a1 = As[k][ty * 2 + 1];
            float4 b0 = *reinterpret_cast<const float4*>(&Bs[k][tx * 8]);
            float4 b1 = *reinterpret_cast<const float4*>(&Bs[k][tx * 8 + 4]);
            float bv[8] = {b0.x, b0.y, b0.z, b0.w, b1.x, b1.y, b1.z, b1.w};
#pragma unroll
            for (int j = 0; j < 8; j++) {
                acc[0][j] = fmaf(a0, bv[j], acc[0][j]);
                acc[1][j] = fmaf(a1, bv[j], acc[1][j]);
            }
        }
        __syncthreads();
    }
#pragma unroll
    for (int i = 0; i < 2; i++) {
        int grow = mBase + ty * 2 + i;
#pragma unroll
        for (int j = 0; j < 8; j++) {
            int gcol = tx * 8 + j;
            float v = acc[i][j] + __ldg(bias + gcol);
            v = (v > 0.f) ? v : expm1f(v);
            C[(size_t)grow * GHD + gcol] = v;
        }
    }
}

// ===========================================================================
// gate3 + softmax (one warp per row)
// ===========================================================================
__global__ void gate3_softmax_kernel(const float* __restrict__ H2,
                                     const float* __restrict__ Wg3,
                                     const float* __restrict__ bg3,
                                     float* __restrict__ BC) {
    int warp = (blockIdx.x * blockDim.x + threadIdx.x) >> 5;
    int lane = threadIdx.x & 31;
    if (warp >= MB) return;
    const float* h = H2 + (size_t)warp * GHD;
    float hv[4];
#pragma unroll
    for (int t = 0; t < 4; t++) hv[t] = h[lane + 32 * t];
    float s[NE];
#pragma unroll
    for (int e = 0; e < NE; e++) {
        float p = 0.f;
#pragma unroll
        for (int t = 0; t < 4; t++)
            p = fmaf(hv[t], __ldg(Wg3 + e * GHD + lane + 32 * t), p);
#pragma unroll
        for (int off = 16; off > 0; off >>= 1) p += __shfl_xor_sync(0xFFFFFFFFu, p, off);
        s[e] = p + __ldg(bg3 + e);
    }
    float mx = s[0];
#pragma unroll
    for (int e = 1; e < NE; e++) mx = fmaxf(mx, s[e]);
    float sum = 0.f;
#pragma unroll
    for (int e = 0; e < NE; e++) { s[e] = expf(s[e] - mx); sum += s[e]; }
    float inv = 1.f / sum;
    if (lane < NE) BC[(size_t)warp * NE + lane] = s[lane] * inv;
}

// ===========================================================================
extern "C" void kernel_launch(void* const* d_in, const int* in_sizes, int n_in,
                              void* d_out, int out_size) {
    const float* x   = (const float*)d_in[0];
    const float* z   = (const float*)d_in[1];
    const float* Wg1 = (const float*)d_in[2];
    const float* bg1 = (const float*)d_in[3];
    const float* Wg2 = (const float*)d_in[4];
    const float* bg2 = (const float*)d_in[5];
    const float* Wg3 = (const float*)d_in[6];
    const float* bg3 = (const float*)d_in[7];
    const float* W0  = (const float*)d_in[8];
    const float* b0  = (const float*)d_in[9];
    const float* W1  = (const float*)d_in[10];
    const float* b1  = (const float*)d_in[11];
    const float* W2  = (const float*)d_in[12];
    const float* b2  = (const float*)d_in[13];
    const float* W3  = (const float*)d_in[14];
    const float* b3  = (const float*)d_in[15];
    float* out = (float*)d_out;

    float *G, *H1, *H2, *BC, *HA, *HB;
    __half *Ah, *Al, *W0h, *W0l, *W1h, *W1l, *W2h, *W2l, *W3h, *W3l;
    cudaGetSymbolAddress((void**)&G,  g_G);
    cudaGetSymbolAddress((void**)&H1, g_H1);
    cudaGetSymbolAddress((void**)&H2, g_H2);
    cudaGetSymbolAddress((void**)&BC, g_BC);
    cudaGetSymbolAddress((void**)&HA, g_HA);
    cudaGetSymbolAddress((void**)&HB, g_HB);
    cudaGetSymbolAddress((void**)&Ah, g_Ah);
    cudaGetSymbolAddress((void**)&Al, g_Al);
    cudaGetSymbolAddress((void**)&W0h, g_W0h);
    cudaGetSymbolAddress((void**)&W0l, g_W0l);
    cudaGetSymbolAddress((void**)&W1h, g_W1h);
    cudaGetSymbolAddress((void**)&W1l, g_W1l);
    cudaGetSymbolAddress((void**)&W2h, g_W2h);
    cudaGetSymbolAddress((void**)&W2l, g_W2l);
    cudaGetSymbolAddress((void**)&W3h, g_W3h);
    cudaGetSymbolAddress((void**)&W3l, g_W3l);

    cudaFuncSetAttribute(moe_hmma_gemm, cudaFuncAttributeMaxDynamicSharedMemorySize, STOTAL);

    // prep
    prep_kernel<<<(MB * GW + 255) / 256, 256>>>(x, z, G, HA, HB);

    // weight splits
    {
        long long t0 = (long long)NE * HD * GW / 4;
        wsplit_kernel<<<(unsigned)((t0 + 255) / 256), 256>>>(W0, W0h, W0l, HD, GW);
        long long t1 = (long long)NE * HD * HW / 4;
        wsplit_kernel<<<(unsigned)((t1 + 255) / 256), 256>>>(W1, W1h, W1l, HD, HW);
        wsplit_kernel<<<(unsigned)((t1 + 255) / 256), 256>>>(W2, W2h, W2l, HD, HW);
        long long t3 = (long long)NE * OD * HD / 4;
        wsplit_kernel<<<(unsigned)((t3 + 255) / 256), 256>>>(W3, W3h, W3l, OD, HD);
    }

    // gate network
    gate_gemm_kernel<<<MB / 32, 256>>>(G, GW, Wg1, bg1, H1);
    gate_gemm_kernel<<<MB / 32, 256>>>(H1, GHD, Wg2, bg2, H2);
    gate3_softmax_kernel<<<(MB * 32 + 255) / 256, 256>>>(H2, Wg3, bg3, BC);

    // layer 0: inp = G [MB,864], Kp = 6912 -> HA[:, :1024], elu
    {
        long long tot = (long long)MB * KP0 / 8;
        asplit_kernel<<<(unsigned)((tot + 255) / 256), 256>>>(G, GW, GW, BC, Ah, Al, KP0);
        moe_hmma_gemm<<<dim3(HD / BN, MB / BM), NTHREADS, STOTAL>>>(
            Ah, Al, W0h, W0l, KP0, b0, BC, HD, HA, HW, 1);
    }
    // layer 1: inp = HA [MB,1088], Kp = 8704 -> HB[:, :1024], elu
    {
        long long tot = (long long)MB * KP1 / 8;
        asplit_kernel<<<(unsigned)((tot + 255) / 256), 256>>>(HA, HW, HW, BC, Ah, Al, KP1);
        moe_hmma_gemm<<<dim3(HD / BN, MB / BM), NTHREADS, STOTAL>>>(
            Ah, Al, W1h, W1l, KP1, b1, BC, HD, HB, HW, 1);
    }
    // layer 2: inp = HB -> HA[:, :1024], elu
    {
        long long tot = (long long)MB * KP1 / 8;
        asplit_kernel<<<(unsigned)((tot + 255) / 256), 256>>>(HB, HW, HW, BC, Ah, Al, KP1);
        moe_hmma_gemm<<<dim3(HD / BN, MB / BM), NTHREADS, STOTAL>>>(
            Ah, Al, W2h, W2l, KP1, b2, BC, HD, HA, HW, 1);
    }
    // layer 3: inp = HA cols 0..1023 (IN=1024, lda=1088), Kp = 8192 -> out, no act
    {
        long long tot = (long long)MB * KP3 / 8;
        asplit_kernel<<<(unsigned)((tot + 255) / 256), 256>>>(HA, HW, HD, BC, Ah, Al, KP3);
        moe_hmma_gemm<<<dim3(OD / BN, MB / BM), NTHREADS, STOTAL>>>(
            Ah, Al, W3h, W3l, KP3, b3, BC, OD, out, OD, 0);
    }
}

// round 6
// speedup vs baseline: 4.3846x; 1.3601x over previous
#include <cuda_runtime.h>
#include <cuda_fp16.h>
#include <math.h>
#include <stdint.h>

// ===========================================================================
// MVAEdecoder via HMMA (mma.sync m16n8k16 fp16, fp32 accum), 2-term split:
//   w = wh + wl (fp16 each), a ~= ah (fp16);  D = ah*wh + ah*wl   (fp32 acc)
// blend(bc,inp,W,b) => GEMM with K' = E*IN; A'[m,e*IN+k] = bc[m,e]*inp[m,k].
// Error ~ 2^-12 relative (A truncation), ~4x under the 1e-3 gate.
// ===========================================================================

#define MB 4096
#define XD 800
#define ZD 64
#define HD 1024
#define OD 768
#define GHD 128
#define NE 8
#define GW (XD + ZD)   // 864
#define HW (HD + ZD)   // 1088

#define KP0 (NE * GW)  // 6912
#define KP1 (NE * HW)  // 8704
#define KP3 (NE * HD)  // 8192

// ---------------- static device scratch ----------------
__device__ __align__(128) float g_G [MB * GW];
__device__ __align__(128) float g_H1[MB * GHD];
__device__ __align__(128) float g_H2[MB * GHD];
__device__ __align__(128) float g_BC[MB * NE];
__device__ __align__(128) float g_HA[MB * HW];
__device__ __align__(128) float g_HB[MB * HW];

// pre-split A' (bc-scaled, expert-replicated), fp16, max K' = 8704
__device__ __align__(128) __half g_Ah[MB * KP1];

// fp16 hi/lo weight copies, layout [Nout][K'=NE*IN]
__device__ __align__(128) __half g_W0h[HD * KP0];
__device__ __align__(128) __half g_W0l[HD * KP0];
__device__ __align__(128) __half g_W1h[HD * KP1];
__device__ __align__(128) __half g_W1l[HD * KP1];
__device__ __align__(128) __half g_W2h[HD * KP1];
__device__ __align__(128) __half g_W2l[HD * KP1];
__device__ __align__(128) __half g_W3h[OD * KP3];
__device__ __align__(128) __half g_W3l[OD * KP3];

// ---------------- PTX helpers ----------------
__device__ __forceinline__ uint32_t smem_u32(const void* p) {
    uint32_t a;
    asm("{ .reg .u64 t; cvta.to.shared.u64 t, %1; cvt.u32.u64 %0, t; }" : "=r"(a) : "l"(p));
    return a;
}

__device__ __forceinline__ void cp_async16(uint32_t dst, const void* src) {
    asm volatile("cp.async.cg.shared.global [%0], [%1], 16;" :: "r"(dst), "l"(src) : "memory");
}
#define CP_COMMIT() asm volatile("cp.async.commit_group;" ::: "memory")
#define CP_WAIT1()  asm volatile("cp.async.wait_group 1;" ::: "memory")
#define CP_WAIT0()  asm volatile("cp.async.wait_group 0;" ::: "memory")

__device__ __forceinline__ void ldsm4(uint32_t* r, uint32_t addr) {
    asm volatile("ldmatrix.sync.aligned.m8n8.x4.shared.b16 {%0,%1,%2,%3}, [%4];"
                 : "=r"(r[0]), "=r"(r[1]), "=r"(r[2]), "=r"(r[3]) : "r"(addr));
}

__device__ __forceinline__ void mma16816(float* c, const uint32_t* a, const uint32_t* b) {
    asm volatile(
        "mma.sync.aligned.m16n8k16.row.col.f32.f16.f16.f32 "
        "{%0,%1,%2,%3}, {%4,%5,%6,%7}, {%8,%9}, {%0,%1,%2,%3};"
        : "+f"(c[0]), "+f"(c[1]), "+f"(c[2]), "+f"(c[3])
        : "r"(a[0]), "r"(a[1]), "r"(a[2]), "r"(a[3]), "r"(b[0]), "r"(b[1]));
}

// ===========================================================================
// prep: G = concat(x,z); fill z-cols of HA/HB
// ===========================================================================
__global__ void prep_kernel(const float* __restrict__ x, const float* __restrict__ z,
                            float* __restrict__ G, float* __restrict__ HA,
                            float* __restrict__ HB) {
    int i = blockIdx.x * blockDim.x + threadIdx.x;
    const int totG = MB * GW;
    if (i < totG) {
        int b = i / GW, c = i - b * GW;
        G[i] = (c < XD) ? x[b * XD + c] : z[b * ZD + (c - XD)];
    }
    const int totZ = MB * ZD;
    if (i < totZ) {
        int b = i / ZD, c = i - b * ZD;
        float v = z[i];
        HA[b * HW + HD + c] = v;
        HB[b * HW + HD + c] = v;
    }
}

// ===========================================================================
// W split: W[e][o][kin] (fp32) -> Wh/Wl[o][e*IN+kin] (fp16 hi/lo)
// ===========================================================================
__global__ void wsplit_kernel(const float* __restrict__ W,
                              __half* __restrict__ Wh, __half* __restrict__ Wl,
                              int Nout, int IN) {
    long long idx = (long long)blockIdx.x * blockDim.x + threadIdx.x;
    long long tot4 = (long long)NE * Nout * IN / 4;
    if (idx >= tot4) return;
    long long i = idx * 4;
    int e = (int)(i / ((long long)Nout * IN));
    long long rem = i - (long long)e * Nout * IN;
    int o = (int)(rem / IN);
    int kin = (int)(rem - (long long)o * IN);
    float4 v = *reinterpret_cast<const float4*>(W + i);
    long long d = (long long)o * ((long long)NE * IN) + e * IN + kin;
    float a[4] = {v.x, v.y, v.z, v.w};
    unsigned short h[4], l[4];
#pragma unroll
    for (int j = 0; j < 4; j++) {
        __half hh = __float2half_rn(a[j]);
        float r = a[j] - __half2float(hh);
        __half ll = __float2half_rn(r);
        h[j] = __half_as_ushort(hh);
        l[j] = __half_as_ushort(ll);
    }
    uint2 hp, lp;
    hp.x = ((uint32_t)h[1] << 16) | h[0]; hp.y = ((uint32_t)h[3] << 16) | h[2];
    lp.x = ((uint32_t)l[1] << 16) | l[0]; lp.y = ((uint32_t)l[3] << 16) | l[2];
    *reinterpret_cast<uint2*>(Wh + d) = hp;
    *reinterpret_cast<uint2*>(Wl + d) = lp;
}

// ===========================================================================
// A split: A[m][kin] (fp32, row stride lda) * bc[m][e] -> Ah[m][e*IN+kin] fp16
// ===========================================================================
__global__ void asplit_kernel(const float* __restrict__ A, int lda, int IN,
                              const float* __restrict__ bc,
                              __half* __restrict__ Ah, int Kp) {
    long long g = (long long)blockIdx.x * blockDim.x + threadIdx.x;
    long long tot = (long long)MB * Kp / 8;
    if (g >= tot) return;
    int segs = Kp >> 3;
    int m = (int)(g / segs);
    int kp = (int)(g - (long long)m * segs) << 3;
    int e = kp / IN;
    int kin = kp - e * IN;
    float sc = __ldg(bc + m * NE + e);
    const float* src = A + (size_t)m * lda + kin;
    float4 v0 = *reinterpret_cast<const float4*>(src);
    float4 v1 = *reinterpret_cast<const float4*>(src + 4);
    float a[8] = {v0.x, v0.y, v0.z, v0.w, v1.x, v1.y, v1.z, v1.w};
    uint32_t hp[4];
#pragma unroll
    for (int j = 0; j < 4; j++) {
        __half h0 = __float2half_rn(a[2 * j] * sc);
        __half h1 = __float2half_rn(a[2 * j + 1] * sc);
        hp[j] = ((uint32_t)__half_as_ushort(h1) << 16) | __half_as_ushort(h0);
    }
    *reinterpret_cast<uint4*>(Ah + (size_t)m * Kp + kp) = make_uint4(hp[0], hp[1], hp[2], hp[3]);
}

// ===========================================================================
// HMMA GEMM: BM=256, BN=128, BK=64, 512 threads (16 warps: 4(M) x 4(N),
// warp tile 64x32). D = ah*wh + ah*wl, both fp32-acc into one accumulator.
// ===========================================================================
#define BM 256
#define BN 128
#define NTHREADS 512

#define SA_OFF    0         // 2 stages x 32768 (A fp16) = 65536
#define SW_OFF    65536     // 2 stages x (hi 16384 + lo 16384) = 65536
#define SBC_OFF   131072    // 256*8*4 = 8192
#define SBIAS_OFF 139264    // 8*128*4 = 4096
#define STOTAL    143360

__device__ __forceinline__ void load_chunk(
    const __half* __restrict__ Ah,
    const __half* __restrict__ Wh, const __half* __restrict__ Wl,
    int Kp, int mBase, int nBase, uint32_t aDst, uint32_t wDst, int kc, int tid)
{
#pragma unroll
    for (int i = 0; i < 4; i++) {
        int lin = tid + i * 512;          // 0..2047
        int r = lin >> 3, ks = lin & 7;
        const __half* src = Ah + (size_t)(mBase + r) * Kp + kc + ks * 8;
        uint32_t dst = aDst + (uint32_t)r * 128u +
                       (((uint32_t)ks * 16u) ^ (((uint32_t)r & 7u) << 4));
        cp_async16(dst, src);
    }
#pragma unroll
    for (int i = 0; i < 4; i++) {
        int lin = tid + i * 512;          // 0..2047
        int hl = lin >> 10;
        int wi = lin & 1023;
        int o = wi >> 3, ks = wi & 7;
        const __half* src = (hl ? Wl : Wh) + (size_t)(nBase + o) * Kp + kc + ks * 8;
        uint32_t dst = wDst + (uint32_t)hl * 16384u + (uint32_t)o * 128u +
                       (((uint32_t)ks * 16u) ^ (((uint32_t)o & 7u) << 4));
        cp_async16(dst, src);
    }
}

__global__ __launch_bounds__(NTHREADS, 1)
void moe_hmma_gemm(const __half* __restrict__ Ah,
                   const __half* __restrict__ Wh, const __half* __restrict__ Wl,
                   int Kp,
                   const float* __restrict__ bias,  // [NE][Nout]
                   const float* __restrict__ bc,    // [MB][NE]
                   int Nout, float* __restrict__ C, int ldc, int applyElu)
{
    extern __shared__ char smem[];
    const uint32_t sb = smem_u32(smem);
    const int tid = threadIdx.x;
    const int lane = tid & 31;
    const int wid = tid >> 5;
    const int wm = wid & 3;       // 0..3 along M (64 rows each)
    const int wn = wid >> 2;      // 0..3 along N (32 cols each)
    const int mBase = blockIdx.y * BM;
    const int nBase = blockIdx.x * BN;
    const int NC = Kp >> 6;

    float* bcs    = reinterpret_cast<float*>(smem + SBC_OFF);   // [256][8]
    float* bias_s = reinterpret_cast<float*>(smem + SBIAS_OFF); // [8][128]
    reinterpret_cast<float4*>(bcs)[tid] =
        reinterpret_cast<const float4*>(bc + (size_t)mBase * NE)[tid];
    if (tid < 256) {
        int e = tid >> 5, cs = (tid & 31) << 2;
        reinterpret_cast<float4*>(bias_s + e * BN + cs)[0] =
            reinterpret_cast<const float4*>(bias + (size_t)e * Nout + nBase + cs)[0];
    }

    // prologue: stage chunks 0 and 1
    load_chunk(Ah, Wh, Wl, Kp, mBase, nBase, sb + SA_OFF, sb + SW_OFF, 0, tid);
    CP_COMMIT();
    load_chunk(Ah, Wh, Wl, Kp, mBase, nBase, sb + SA_OFF + 32768u,
               sb + SW_OFF + 32768u, 64, tid);
    CP_COMMIT();
    CP_WAIT1();
    __syncthreads();

    float acc[4][4][4];
#pragma unroll
    for (int a = 0; a < 4; a++)
#pragma unroll
        for (int b = 0; b < 4; b++)
#pragma unroll
            for (int q = 0; q < 4; q++) acc[a][b][q] = 0.f;

    // per-thread ldmatrix address pieces
    const int aRow = wm * 64 + (lane & 15);
    const uint32_t aXor = ((uint32_t)aRow & 7u) << 4;
    const uint32_t aKb = ((uint32_t)lane >> 4) << 4;
    const uint32_t aRowOff = (uint32_t)aRow * 128u;
    const int bRow = wn * 32 + (lane & 7) + (((lane >> 4) & 1) << 3);
    const uint32_t bXor = ((uint32_t)bRow & 7u) << 4;
    const uint32_t bKb = (((uint32_t)lane >> 3) & 1u) << 4;
    const uint32_t bRowOff = (uint32_t)bRow * 128u;

    for (int c = 0; c < NC; c++) {
        const int st = c & 1;
        const uint32_t aSt = sb + SA_OFF + (uint32_t)st * 32768u;
        const uint32_t wSt = sb + SW_OFF + (uint32_t)st * 32768u;

#pragma unroll
        for (int kk = 0; kk < 4; kk++) {
            const uint32_t kA = ((uint32_t)(kk * 32) + aKb) ^ aXor;
            const uint32_t kB = ((uint32_t)(kk * 32) + bKb) ^ bXor;
            uint32_t bfh[8], bfl[8], af[4][4];
#pragma unroll
            for (int g = 0; g < 2; g++) {
                ldsm4(&bfh[4 * g], wSt + bRowOff + (uint32_t)g * 2048u + kB);
                ldsm4(&bfl[4 * g], wSt + 16384u + bRowOff + (uint32_t)g * 2048u + kB);
            }
#pragma unroll
            for (int mf = 0; mf < 4; mf++)
                ldsm4(af[mf], aSt + aRowOff + (uint32_t)mf * 2048u + kA);
#pragma unroll
            for (int mf = 0; mf < 4; mf++)
#pragma unroll
                for (int nf = 0; nf < 4; nf++)
                    mma16816(acc[mf][nf], af[mf], &bfh[2 * nf]);
#pragma unroll
            for (int mf = 0; mf < 4; mf++)
#pragma unroll
                for (int nf = 0; nf < 4; nf++)
                    mma16816(acc[mf][nf], af[mf], &bfl[2 * nf]);
        }

        __syncthreads();
        if (c + 2 < NC) {
            load_chunk(Ah, Wh, Wl, Kp, mBase, nBase, aSt, wSt, (c + 2) * 64, tid);
            CP_COMMIT();
            CP_WAIT1();
        } else {
            CP_WAIT0();
        }
        __syncthreads();
    }

    // ---- epilogue: blended bias + ELU, direct float2 stores ----
#pragma unroll
    for (int mf = 0; mf < 4; mf++) {
        const int r0 = wm * 64 + mf * 16 + (lane >> 2);
        const int r1 = r0 + 8;
        float bcv0[NE], bcv1[NE];
#pragma unroll
        for (int e = 0; e < NE; e++) { bcv0[e] = bcs[r0 * 8 + e]; bcv1[e] = bcs[r1 * 8 + e]; }
#pragma unroll
        for (int nf = 0; nf < 4; nf++) {
            const int cl = wn * 32 + nf * 8 + ((lane & 3) << 1);
            float bb00 = 0.f, bb01 = 0.f, bb10 = 0.f, bb11 = 0.f;
#pragma unroll
            for (int e = 0; e < NE; e++) {
                float be0 = bias_s[e * BN + cl], be1 = bias_s[e * BN + cl + 1];
                bb00 = fmaf(bcv0[e], be0, bb00);
                bb01 = fmaf(bcv0[e], be1, bb01);
                bb10 = fmaf(bcv1[e], be0, bb10);
                bb11 = fmaf(bcv1[e], be1, bb11);
            }
            float v00 = acc[mf][nf][0] + bb00;
            float v01 = acc[mf][nf][1] + bb01;
            float v10 = acc[mf][nf][2] + bb10;
            float v11 = acc[mf][nf][3] + bb11;
            if (applyElu) {
                v00 = (v00 > 0.f) ? v00 : expm1f(v00);
                v01 = (v01 > 0.f) ? v01 : expm1f(v01);
                v10 = (v10 > 0.f) ? v10 : expm1f(v10);
                v11 = (v11 > 0.f) ? v11 : expm1f(v11);
            }
            const int gc = nBase + cl;
            *reinterpret_cast<float2*>(C + (size_t)(mBase + r0) * ldc + gc) =
                make_float2(v00, v01);
            *reinterpret_cast<float2*>(C + (size_t)(mBase + r1) * ldc + gc) =
                make_float2(v10, v11);
        }
    }
}

// ===========================================================================
// gate GEMM: BM=32, BN=128(=Nout), BK=16, elu. grid = 4096/32 = 128
// ===========================================================================
__global__ __launch_bounds__(256, 4)
void gate_gemm_kernel(const float* __restrict__ A, int IN,
                      const float* __restrict__ W,   // [128][IN]
                      const float* __restrict__ bias,
                      float* __restrict__ C) {
    __shared__ float As[16][32];
    __shared__ float Bs[16][128];
    const int tid = threadIdx.x;
    const int tx = tid & 15, ty = tid >> 4;
    const int mBase = blockIdx.x * 32;

    float acc[2][8];
#pragma unroll
    for (int i = 0; i < 2; i++)
#pragma unroll
        for (int j = 0; j < 8; j++) acc[i][j] = 0.f;

    const int r2 = tid >> 2;
    const int vec = (tid & 3) << 2;

    for (int k0 = 0; k0 < IN; k0 += 16) {
        if (tid < 128) {
            int r = tid >> 2;
            float4 v = *reinterpret_cast<const float4*>(A + (size_t)(mBase + r) * IN + k0 + vec);
            As[vec + 0][r] = v.x; As[vec + 1][r] = v.y;
            As[vec + 2][r] = v.z; As[vec + 3][r] = v.w;
        }
#pragma unroll
        for (int rr = 0; rr < 2; rr++) {
            int o = r2 + rr * 64;
            float4 v = *reinterpret_cast<const float4*>(W + (size_t)o * IN + k0 + vec);
            Bs[vec + 0][o] = v.x; Bs[vec + 1][o] = v.y;
            Bs[vec + 2][o] = v.z; Bs[vec + 3][o] = v.w;
        }
        __syncthreads();
#pragma unroll
        for (int k = 0; k < 16; k++) {
            float a0 = As[k][ty * 2], a1 = As[k][ty * 2 + 1];
            float4 b0 = *reinterpret_cast<const float4*>(&Bs[k][tx * 8]);
            float4 b1 = *reinterpret_cast<const float4*>(&Bs[k][tx * 8 + 4]);
            float bv[8] = {b0.x, b0.y, b0.z, b0.w, b1.x, b1.y, b1.z, b1.w};
#pragma unroll
            for (int j = 0; j < 8; j++) {
                acc[0][j] = fmaf(a0, bv[j], acc[0][j]);
                acc[1][j] = fmaf(a1, bv[j], acc[1][j]);
            }
        }
        __syncthreads();
    }
#pragma unroll
    for (int i = 0; i < 2; i++) {
        int grow = mBase + ty * 2 + i;
#pragma unroll
        for (int j = 0; j < 8; j++) {
            int gcol = tx * 8 + j;
            float v = acc[i][j] + __ldg(bias + gcol);
            v = (v > 0.f) ? v : expm1f(v);
            C[(size_t)grow * GHD + gcol] = v;
        }
    }
}

// ===========================================================================
// gate3 + softmax (one warp per row)
// ===========================================================================
__global__ void gate3_softmax_kernel(const float* __restrict__ H2,
                                     const float* __restrict__ Wg3,
                                     const float* __restrict__ bg3,
                                     float* __restrict__ BC) {
    int warp = (blockIdx.x * blockDim.x + threadIdx.x) >> 5;
    int lane = threadIdx.x & 31;
    if (warp >= MB) return;
    const float* h = H2 + (size_t)warp * GHD;
    float hv[4];
#pragma unroll
    for (int t = 0; t < 4; t++) hv[t] = h[lane + 32 * t];
    float s[NE];
#pragma unroll
    for (int e = 0; e < NE; e++) {
        float p = 0.f;
#pragma unroll
        for (int t = 0; t < 4; t++)
            p = fmaf(hv[t], __ldg(Wg3 + e * GHD + lane + 32 * t), p);
#pragma unroll
        for (int off = 16; off > 0; off >>= 1) p += __shfl_xor_sync(0xFFFFFFFFu, p, off);
        s[e] = p + __ldg(bg3 + e);
    }
    float mx = s[0];
#pragma unroll
    for (int e = 1; e < NE; e++) mx = fmaxf(mx, s[e]);
    float sum = 0.f;
#pragma unroll
    for (int e = 0; e < NE; e++) { s[e] = expf(s[e] - mx); sum += s[e]; }
    float inv = 1.f / sum;
    if (lane < NE) BC[(size_t)warp * NE + lane] = s[lane] * inv;
}

// ===========================================================================
extern "C" void kernel_launch(void* const* d_in, const int* in_sizes, int n_in,
                              void* d_out, int out_size) {
    const float* x   = (const float*)d_in[0];
    const float* z   = (const float*)d_in[1];
    const float* Wg1 = (const float*)d_in[2];
    const float* bg1 = (const float*)d_in[3];
    const float* Wg2 = (const float*)d_in[4];
    const float* bg2 = (const float*)d_in[5];
    const float* Wg3 = (const float*)d_in[6];
    const float* bg3 = (const float*)d_in[7];
    const float* W0  = (const float*)d_in[8];
    const float* b0  = (const float*)d_in[9];
    const float* W1  = (const float*)d_in[10];
    const float* b1  = (const float*)d_in[11];
    const float* W2  = (const float*)d_in[12];
    const float* b2  = (const float*)d_in[13];
    const float* W3  = (const float*)d_in[14];
    const float* b3  = (const float*)d_in[15];
    float* out = (float*)d_out;

    float *G, *H1, *H2, *BC, *HA, *HB;
    __half *Ah, *W0h, *W0l, *W1h, *W1l, *W2h, *W2l, *W3h, *W3l;
    cudaGetSymbolAddress((void**)&G,  g_G);
    cudaGetSymbolAddress((void**)&H1, g_H1);
    cudaGetSymbolAddress((void**)&H2, g_H2);
    cudaGetSymbolAddress((void**)&BC, g_BC);
    cudaGetSymbolAddress((void**)&HA, g_HA);
    cudaGetSymbolAddress((void**)&HB, g_HB);
    cudaGetSymbolAddress((void**)&Ah, g_Ah);
    cudaGetSymbolAddress((void**)&W0h, g_W0h);
    cudaGetSymbolAddress((void**)&W0l, g_W0l);
    cudaGetSymbolAddress((void**)&W1h, g_W1h);
    cudaGetSymbolAddress((void**)&W1l, g_W1l);
    cudaGetSymbolAddress((void**)&W2h, g_W2h);
    cudaGetSymbolAddress((void**)&W2l, g_W2l);
    cudaGetSymbolAddress((void**)&W3h, g_W3h);
    cudaGetSymbolAddress((void**)&W3l, g_W3l);

    cudaFuncSetAttribute(moe_hmma_gemm, cudaFuncAttributeMaxDynamicSharedMemorySize, STOTAL);

    // prep
    prep_kernel<<<(MB * GW + 255) / 256, 256>>>(x, z, G, HA, HB);

    // weight splits
    {
        long long t0 = (long long)NE * HD * GW / 4;
        wsplit_kernel<<<(unsigned)((t0 + 255) / 256), 256>>>(W0, W0h, W0l, HD, GW);
        long long t1 = (long long)NE * HD * HW / 4;
        wsplit_kernel<<<(unsigned)((t1 + 255) / 256), 256>>>(W1, W1h, W1l, HD, HW);
        wsplit_kernel<<<(unsigned)((t1 + 255) / 256), 256>>>(W2, W2h, W2l, HD, HW);
        long long t3 = (long long)NE * OD * HD / 4;
        wsplit_kernel<<<(unsigned)((t3 + 255) / 256), 256>>>(W3, W3h, W3l, OD, HD);
    }

    // gate network
    gate_gemm_kernel<<<MB / 32, 256>>>(G, GW, Wg1, bg1, H1);
    gate_gemm_kernel<<<MB / 32, 256>>>(H1, GHD, Wg2, bg2, H2);
    gate3_softmax_kernel<<<(MB * 32 + 255) / 256, 256>>>(H2, Wg3, bg3, BC);

    // layer 0: inp = G [MB,864], Kp = 6912 -> HA[:, :1024], elu
    {
        long long tot = (long long)MB * KP0 / 8;
        asplit_kernel<<<(unsigned)((tot + 255) / 256), 256>>>(G, GW, GW, BC, Ah, KP0);
        moe_hmma_gemm<<<dim3(HD / BN, MB / BM), NTHREADS, STOTAL>>>(
            Ah, W0h, W0l, KP0, b0, BC, HD, HA, HW, 1);
    }
    // layer 1: inp = HA [MB,1088], Kp = 8704 -> HB[:, :1024], elu
    {
        long long tot = (long long)MB * KP1 / 8;
        asplit_kernel<<<(unsigned)((tot + 255) / 256), 256>>>(HA, HW, HW, BC, Ah, KP1);
        moe_hmma_gemm<<<dim3(HD / BN, MB / BM), NTHREADS, STOTAL>>>(
            Ah, W1h, W1l, KP1, b1, BC, HD, HB, HW, 1);
    }
    // layer 2: inp = HB -> HA[:, :1024], elu
    {
        long long tot = (long long)MB * KP1 / 8;
        asplit_kernel<<<(unsigned)((tot + 255) / 256), 256>>>(HB, HW, HW, BC, Ah, KP1);
        moe_hmma_gemm<<<dim3(HD / BN, MB / BM), NTHREADS, STOTAL>>>(
            Ah, W2h, W2l, KP1, b2, BC, HD, HA, HW, 1);
    }
    // layer 3: inp = HA cols 0..1023 (IN=1024, lda=1088), Kp = 8192 -> out, no act
    {
        long long tot = (long long)MB * KP3 / 8;
        asplit_kernel<<<(unsigned)((tot + 255) / 256), 256>>>(HA, HW, HD, BC, Ah, KP3);
        moe_hmma_gemm<<<dim3(OD / BN, MB / BM), NTHREADS, STOTAL>>>(
            Ah, W3h, W3l, KP3, b3, BC, OD, out, OD, 0);
    }
}

// round 7
// speedup vs baseline: 7.4180x; 1.6918x over previous
#include <cuda_runtime.h>
#include <cuda_fp16.h>
#include <math.h>
#include <stdint.h>

// ===========================================================================
// MVAEdecoder via HMMA (mma.sync m16n8k16 fp16, fp32 accum), single-term:
//   D = fp16(bc*a) @ fp16(W)^T   (fp32 accumulate)
// blend(bc,inp,W,b) => GEMM with K' = E*IN; A'[m,e*IN+k] = bc[m,e]*inp[m,k].
// Calibrated error: A-trunc ~3.3e-4 + W-trunc ~3.3e-4 (RSS ~4.7e-4) < 1e-3.
// ===========================================================================

#define MB 4096
#define XD 800
#define ZD 64
#define HD 1024
#define OD 768
#define GHD 128
#define NE 8
#define GW (XD + ZD)   // 864
#define HW (HD + ZD)   // 1088

#define KP0 (NE * GW)  // 6912
#define KP1 (NE * HW)  // 8704
#define KP3 (NE * HD)  // 8192

// ---------------- static device scratch ----------------
__device__ __align__(128) float g_G [MB * GW];
__device__ __align__(128) float g_H1[MB * GHD];
__device__ __align__(128) float g_H2[MB * GHD];
__device__ __align__(128) float g_BC[MB * NE];
__device__ __align__(128) float g_HA[MB * HW];
__device__ __align__(128) float g_HB[MB * HW];

// pre-split A' (bc-scaled, expert-replicated), fp16, max K' = 8704
__device__ __align__(128) __half g_Ah[MB * KP1];

// fp16 weight copies, layout [Nout][K'=NE*IN]
__device__ __align__(128) __half g_W0h[HD * KP0];
__device__ __align__(128) __half g_W1h[HD * KP1];
__device__ __align__(128) __half g_W2h[HD * KP1];
__device__ __align__(128) __half g_W3h[OD * KP3];

// ---------------- PTX helpers ----------------
__device__ __forceinline__ uint32_t smem_u32(const void* p) {
    uint32_t a;
    asm("{ .reg .u64 t; cvta.to.shared.u64 t, %1; cvt.u32.u64 %0, t; }" : "=r"(a) : "l"(p));
    return a;
}

__device__ __forceinline__ void cp_async16(uint32_t dst, const void* src) {
    asm volatile("cp.async.cg.shared.global [%0], [%1], 16;" :: "r"(dst), "l"(src) : "memory");
}
#define CP_COMMIT() asm volatile("cp.async.commit_group;" ::: "memory")
#define CP_WAIT1()  asm volatile("cp.async.wait_group 1;" ::: "memory")
#define CP_WAIT0()  asm volatile("cp.async.wait_group 0;" ::: "memory")

__device__ __forceinline__ void ldsm4(uint32_t* r, uint32_t addr) {
    asm volatile("ldmatrix.sync.aligned.m8n8.x4.shared.b16 {%0,%1,%2,%3}, [%4];"
                 : "=r"(r[0]), "=r"(r[1]), "=r"(r[2]), "=r"(r[3]) : "r"(addr));
}

__device__ __forceinline__ void mma16816(float* c, const uint32_t* a, const uint32_t* b) {
    asm volatile(
        "mma.sync.aligned.m16n8k16.row.col.f32.f16.f16.f32 "
        "{%0,%1,%2,%3}, {%4,%5,%6,%7}, {%8,%9}, {%0,%1,%2,%3};"
        : "+f"(c[0]), "+f"(c[1]), "+f"(c[2]), "+f"(c[3])
        : "r"(a[0]), "r"(a[1]), "r"(a[2]), "r"(a[3]), "r"(b[0]), "r"(b[1]));
}

// ===========================================================================
// prep: G = concat(x,z); fill z-cols of HA/HB
// ===========================================================================
__global__ void prep_kernel(const float* __restrict__ x, const float* __restrict__ z,
                            float* __restrict__ G, float* __restrict__ HA,
                            float* __restrict__ HB) {
    int i = blockIdx.x * blockDim.x + threadIdx.x;
    const int totG = MB * GW;
    if (i < totG) {
        int b = i / GW, c = i - b * GW;
        G[i] = (c < XD) ? x[b * XD + c] : z[b * ZD + (c - XD)];
    }
    const int totZ = MB * ZD;
    if (i < totZ) {
        int b = i / ZD, c = i - b * ZD;
        float v = z[i];
        HA[b * HW + HD + c] = v;
        HB[b * HW + HD + c] = v;
    }
}

// ===========================================================================
// W convert: W[e][o][kin] (fp32) -> Wh[o][e*IN+kin] (fp16)
// ===========================================================================
__global__ void wconv_kernel(const float* __restrict__ W,
                             __half* __restrict__ Wh, int Nout, int IN) {
    long long idx = (long long)blockIdx.x * blockDim.x + threadIdx.x;
    long long tot4 = (long long)NE * Nout * IN / 4;
    if (idx >= tot4) return;
    long long i = idx * 4;
    int e = (int)(i / ((long long)Nout * IN));
    long long rem = i - (long long)e * Nout * IN;
    int o = (int)(rem / IN);
    int kin = (int)(rem - (long long)o * IN);
    float4 v = *reinterpret_cast<const float4*>(W + i);
    long long d = (long long)o * ((long long)NE * IN) + e * IN + kin;
    unsigned short h[4];
    h[0] = __half_as_ushort(__float2half_rn(v.x));
    h[1] = __half_as_ushort(__float2half_rn(v.y));
    h[2] = __half_as_ushort(__float2half_rn(v.z));
    h[3] = __half_as_ushort(__float2half_rn(v.w));
    uint2 hp;
    hp.x = ((uint32_t)h[1] << 16) | h[0]; hp.y = ((uint32_t)h[3] << 16) | h[2];
    *reinterpret_cast<uint2*>(Wh + d) = hp;
}

// ===========================================================================
// A split: A[m][kin] (fp32, row stride lda) * bc[m][e] -> Ah[m][e*IN+kin] fp16
// ===========================================================================
__global__ void asplit_kernel(const float* __restrict__ A, int lda, int IN,
                              const float* __restrict__ bc,
                              __half* __restrict__ Ah, int Kp) {
    long long g = (long long)blockIdx.x * blockDim.x + threadIdx.x;
    long long tot = (long long)MB * Kp / 8;
    if (g >= tot) return;
    int segs = Kp >> 3;
    int m = (int)(g / segs);
    int kp = (int)(g - (long long)m * segs) << 3;
    int e = kp / IN;
    int kin = kp - e * IN;
    float sc = __ldg(bc + m * NE + e);
    const float* src = A + (size_t)m * lda + kin;
    float4 v0 = *reinterpret_cast<const float4*>(src);
    float4 v1 = *reinterpret_cast<const float4*>(src + 4);
    float a[8] = {v0.x, v0.y, v0.z, v0.w, v1.x, v1.y, v1.z, v1.w};
    uint32_t hp[4];
#pragma unroll
    for (int j = 0; j < 4; j++) {
        __half h0 = __float2half_rn(a[2 * j] * sc);
        __half h1 = __float2half_rn(a[2 * j + 1] * sc);
        hp[j] = ((uint32_t)__half_as_ushort(h1) << 16) | __half_as_ushort(h0);
    }
    *reinterpret_cast<uint4*>(Ah + (size_t)m * Kp + kp) = make_uint4(hp[0], hp[1], hp[2], hp[3]);
}

// ===========================================================================
// HMMA GEMM: BM=256, BN=128, BK=64, 512 threads (16 warps: 4(M) x 4(N),
// warp tile 64x32). Single term, fp32 accumulate.
// ===========================================================================
#define BM 256
#define BN 128
#define NTHREADS 512

#define SA_OFF    0         // 2 stages x 32768 (A fp16) = 65536
#define SW_OFF    65536     // 2 stages x 16384 (W fp16) = 32768
#define SBC_OFF   98304     // 256*8*4 = 8192
#define SBIAS_OFF 106496    // 8*128*4 = 4096
#define STOTAL    110592

__device__ __forceinline__ void load_chunk(
    const __half* __restrict__ Ah, const __half* __restrict__ Wh,
    int Kp, int mBase, int nBase, uint32_t aDst, uint32_t wDst, int kc, int tid)
{
#pragma unroll
    for (int i = 0; i < 4; i++) {
        int lin = tid + i * 512;          // 0..2047
        int r = lin >> 3, ks = lin & 7;
        const __half* src = Ah + (size_t)(mBase + r) * Kp + kc + ks * 8;
        uint32_t dst = aDst + (uint32_t)r * 128u +
                       (((uint32_t)ks * 16u) ^ (((uint32_t)r & 7u) << 4));
        cp_async16(dst, src);
    }
#pragma unroll
    for (int i = 0; i < 2; i++) {
        int lin = tid + i * 512;          // 0..1023
        int o = lin >> 3, ks = lin & 7;
        const __half* src = Wh + (size_t)(nBase + o) * Kp + kc + ks * 8;
        uint32_t dst = wDst + (uint32_t)o * 128u +
                       (((uint32_t)ks * 16u) ^ (((uint32_t)o & 7u) << 4));
        cp_async16(dst, src);
    }
}

__global__ __launch_bounds__(NTHREADS, 1)
void moe_hmma_gemm(const __half* __restrict__ Ah, const __half* __restrict__ Wh,
                   int Kp,
                   const float* __restrict__ bias,  // [NE][Nout]
                   const float* __restrict__ bc,    // [MB][NE]
                   int Nout, float* __restrict__ C, int ldc, int applyElu)
{
    extern __shared__ char smem[];
    const uint32_t sb = smem_u32(smem);
    const int tid = threadIdx.x;
    const int lane = tid & 31;
    const int wid = tid >> 5;
    const int wm = wid & 3;       // 0..3 along M (64 rows each)
    const int wn = wid >> 2;      // 0..3 along N (32 cols each)
    const int mBase = blockIdx.y * BM;
    const int nBase = blockIdx.x * BN;
    const int NC = Kp >> 6;

    float* bcs    = reinterpret_cast<float*>(smem + SBC_OFF);   // [256][8]
    float* bias_s = reinterpret_cast<float*>(smem + SBIAS_OFF); // [8][128]
    reinterpret_cast<float4*>(bcs)[tid] =
        reinterpret_cast<const float4*>(bc + (size_t)mBase * NE)[tid];
    if (tid < 256) {
        int e = tid >> 5, cs = (tid & 31) << 2;
        reinterpret_cast<float4*>(bias_s + e * BN + cs)[0] =
            reinterpret_cast<const float4*>(bias + (size_t)e * Nout + nBase + cs)[0];
    }

    // prologue: stage chunks 0 and 1
    load_chunk(Ah, Wh, Kp, mBase, nBase, sb + SA_OFF, sb + SW_OFF, 0, tid);
    CP_COMMIT();
    load_chunk(Ah, Wh, Kp, mBase, nBase, sb + SA_OFF + 32768u,
               sb + SW_OFF + 16384u, 64, tid);
    CP_COMMIT();
    CP_WAIT1();
    __syncthreads();

    float acc[4][4][4];
#pragma unroll
    for (int a = 0; a < 4; a++)
#pragma unroll
        for (int b = 0; b < 4; b++)
#pragma unroll
            for (int q = 0; q < 4; q++) acc[a][b][q] = 0.f;

    // per-thread ldmatrix address pieces
    const int aRow = wm * 64 + (lane & 15);
    const uint32_t aXor = ((uint32_t)aRow & 7u) << 4;
    const uint32_t aKb = ((uint32_t)lane >> 4) << 4;
    const uint32_t aRowOff = (uint32_t)aRow * 128u;
    const int bRow = wn * 32 + (lane & 7) + (((lane >> 4) & 1) << 3);
    const uint32_t bXor = ((uint32_t)bRow & 7u) << 4;
    const uint32_t bKb = (((uint32_t)lane >> 3) & 1u) << 4;
    const uint32_t bRowOff = (uint32_t)bRow * 128u;

    for (int c = 0; c < NC; c++) {
        const int st = c & 1;
        const uint32_t aSt = sb + SA_OFF + (uint32_t)st * 32768u;
        const uint32_t wSt = sb + SW_OFF + (uint32_t)st * 16384u;

#pragma unroll
        for (int kk = 0; kk < 4; kk++) {
            const uint32_t kA = ((uint32_t)(kk * 32) + aKb) ^ aXor;
            const uint32_t kB = ((uint32_t)(kk * 32) + bKb) ^ bXor;
            uint32_t bfh[8], af[4][4];
#pragma unroll
            for (int g = 0; g < 2; g++)
                ldsm4(&bfh[4 * g], wSt + bRowOff + (uint32_t)g * 2048u + kB);
#pragma unroll
            for (int mf = 0; mf < 4; mf++)
                ldsm4(af[mf], aSt + aRowOff + (uint32_t)mf * 2048u + kA);
#pragma unroll
            for (int mf = 0; mf < 4; mf++)
#pragma unroll
                for (int nf = 0; nf < 4; nf++)
                    mma16816(acc[mf][nf], af[mf], &bfh[2 * nf]);
        }

        __syncthreads();
        if (c + 2 < NC) {
            load_chunk(Ah, Wh, Kp, mBase, nBase, aSt, wSt, (c + 2) * 64, tid);
            CP_COMMIT();
            CP_WAIT1();
        } else {
            CP_WAIT0();
        }
        __syncthreads();
    }

    // ---- epilogue: blended bias + ELU, direct float2 stores ----
#pragma unroll
    for (int mf = 0; mf < 4; mf++) {
        const int r0 = wm * 64 + mf * 16 + (lane >> 2);
        const int r1 = r0 + 8;
        float bcv0[NE], bcv1[NE];
#pragma unroll
        for (int e = 0; e < NE; e++) { bcv0[e] = bcs[r0 * 8 + e]; bcv1[e] = bcs[r1 * 8 + e]; }
#pragma unroll
        for (int nf = 0; nf < 4; nf++) {
            const int cl = wn * 32 + nf * 8 + ((lane & 3) << 1);
            float bb00 = 0.f, bb01 = 0.f, bb10 = 0.f, bb11 = 0.f;
#pragma unroll
            for (int e = 0; e < NE; e++) {
                float be0 = bias_s[e * BN + cl], be1 = bias_s[e * BN + cl + 1];
                bb00 = fmaf(bcv0[e], be0, bb00);
                bb01 = fmaf(bcv0[e], be1, bb01);
                bb10 = fmaf(bcv1[e], be0, bb10);
                bb11 = fmaf(bcv1[e], be1, bb11);
            }
            float v00 = acc[mf][nf][0] + bb00;
            float v01 = acc[mf][nf][1] + bb01;
            float v10 = acc[mf][nf][2] + bb10;
            float v11 = acc[mf][nf][3] + bb11;
            if (applyElu) {
                v00 = (v00 > 0.f) ? v00 : expm1f(v00);
                v01 = (v01 > 0.f) ? v01 : expm1f(v01);
                v10 = (v10 > 0.f) ? v10 : expm1f(v10);
                v11 = (v11 > 0.f) ? v11 : expm1f(v11);
            }
            const int gc = nBase + cl;
            *reinterpret_cast<float2*>(C + (size_t)(mBase + r0) * ldc + gc) =
                make_float2(v00, v01);
            *reinterpret_cast<float2*>(C + (size_t)(mBase + r1) * ldc + gc) =
                make_float2(v10, v11);
        }
    }
}

// ===========================================================================
// gate GEMM: BM=32, BN=128(=Nout), BK=16, elu. grid = 4096/32 = 128
// ===========================================================================
__global__ __launch_bounds__(256, 4)
void gate_gemm_kernel(const float* __restrict__ A, int IN,
                      const float* __restrict__ W,   // [128][IN]
                      const float* __restrict__ bias,
                      float* __restrict__ C) {
    __shared__ float As[16][32];
    __shared__ float Bs[16][128];
    const int tid = threadIdx.x;
    const int tx = tid & 15, ty = tid >> 4;
    const int mBase = blockIdx.x * 32;

    float acc[2][8];
#pragma unroll
    for (int i = 0; i < 2; i++)
#pragma unroll
        for (int j = 0; j < 8; j++) acc[i][j] = 0.f;

    const int r2 = tid >> 2;
    const int vec = (tid & 3) << 2;

    for (int k0 = 0; k0 < IN; k0 += 16) {
        if (tid < 128) {
            int r = tid >> 2;
            float4 v = *reinterpret_cast<const float4*>(A + (size_t)(mBase + r) * IN + k0 + vec);
            As[vec + 0][r] = v.x; As[vec + 1][r] = v.y;
            As[vec + 2][r] = v.z; As[vec + 3][r] = v.w;
        }
#pragma unroll
        for (int rr = 0; rr < 2; rr++) {
            int o = r2 + rr * 64;
            float4 v = *reinterpret_cast<const float4*>(W + (size_t)o * IN + k0 + vec);
            Bs[vec + 0][o] = v.x; Bs[vec + 1][o] = v.y;
            Bs[vec + 2][o] = v.z; Bs[vec + 3][o] = v.w;
        }
        __syncthreads();
#pragma unroll
        for (int k = 0; k < 16; k++) {
            float a0 = As[k][ty * 2], a1 = As[k][ty * 2 + 1];
            float4 b0 = *reinterpret_cast<const float4*>(&Bs[k][tx * 8]);
            float4 b1 = *reinterpret_cast<const float4*>(&Bs[k][tx * 8 + 4]);
            float bv[8] = {b0.x, b0.y, b0.z, b0.w, b1.x, b1.y, b1.z, b1.w};
#pragma unroll
            for (int j = 0; j < 8; j++) {
                acc[0][j] = fmaf(a0, bv[j], acc[0][j]);
                acc[1][j] = fmaf(a1, bv[j], acc[1][j]);
            }
        }
        __syncthreads();
    }
#pragma unroll
    for (int i = 0; i < 2; i++) {
        int grow = mBase + ty * 2 + i;
#pragma unroll
        for (int j = 0; j < 8; j++) {
            int gcol = tx * 8 + j;
            float v = acc[i][j] + __ldg(bias + gcol);
            v = (v > 0.f) ? v : expm1f(v);
            C[(size_t)grow * GHD + gcol] = v;
        }
    }
}

// ===========================================================================
// gate3 + softmax (one warp per row)
// ===========================================================================
__global__ void gate3_softmax_kernel(const float* __restrict__ H2,
                                     const float* __restrict__ Wg3,
                                     const float* __restrict__ bg3,
                                     float* __restrict__ BC) {
    int warp = (blockIdx.x * blockDim.x + threadIdx.x) >> 5;
    int lane = threadIdx.x & 31;
    if (warp >= MB) return;
    const float* h = H2 + (size_t)warp * GHD;
    float hv[4];
#pragma unroll
    for (int t = 0; t < 4; t++) hv[t] = h[lane + 32 * t];
    float s[NE];
#pragma unroll
    for (int e = 0; e < NE; e++) {
        float p = 0.f;
#pragma unroll
        for (int t = 0; t < 4; t++)
            p = fmaf(hv[t], __ldg(Wg3 + e * GHD + lane + 32 * t), p);
#pragma unroll
        for (int off = 16; off > 0; off >>= 1) p += __shfl_xor_sync(0xFFFFFFFFu, p, off);
        s[e] = p + __ldg(bg3 + e);
    }
    float mx = s[0];
#pragma unroll
    for (int e = 1; e < NE; e++) mx = fmaxf(mx, s[e]);
    float sum = 0.f;
#pragma unroll
    for (int e = 0; e < NE; e++) { s[e] = expf(s[e] - mx); sum += s[e]; }
    float inv = 1.f / sum;
    if (lane < NE) BC[(size_t)warp * NE + lane] = s[lane] * inv;
}

// ===========================================================================
extern "C" void kernel_launch(void* const* d_in, const int* in_sizes, int n_in,
                              void* d_out, int out_size) {
    const float* x   = (const float*)d_in[0];
    const float* z   = (const float*)d_in[1];
    const float* Wg1 = (const float*)d_in[2];
    const float* bg1 = (const float*)d_in[3];
    const float* Wg2 = (const float*)d_in[4];
    const float* bg2 = (const float*)d_in[5];
    const float* Wg3 = (const float*)d_in[6];
    const float* bg3 = (const float*)d_in[7];
    const float* W0  = (const float*)d_in[8];
    const float* b0  = (const float*)d_in[9];
    const float* W1  = (const float*)d_in[10];
    const float* b1  = (const float*)d_in[11];
    const float* W2  = (const float*)d_in[12];
    const float* b2  = (const float*)d_in[13];
    const float* W3  = (const float*)d_in[14];
    const float* b3  = (const float*)d_in[15];
    float* out = (float*)d_out;

    float *G, *H1, *H2, *BC, *HA, *HB;
    __half *Ah, *W0h, *W1h, *W2h, *W3h;
    cudaGetSymbolAddress((void**)&G,  g_G);
    cudaGetSymbolAddress((void**)&H1, g_H1);
    cudaGetSymbolAddress((void**)&H2, g_H2);
    cudaGetSymbolAddress((void**)&BC, g_BC);
    cudaGetSymbolAddress((void**)&HA, g_HA);
    cudaGetSymbolAddress((void**)&HB, g_HB);
    cudaGetSymbolAddress((void**)&Ah, g_Ah);
    cudaGetSymbolAddress((void**)&W0h, g_W0h);
    cudaGetSymbolAddress((void**)&W1h, g_W1h);
    cudaGetSymbolAddress((void**)&W2h, g_W2h);
    cudaGetSymbolAddress((void**)&W3h, g_W3h);

    cudaFuncSetAttribute(moe_hmma_gemm, cudaFuncAttributeMaxDynamicSharedMemorySize, STOTAL);

    // prep
    prep_kernel<<<(MB * GW + 255) / 256, 256>>>(x, z, G, HA, HB);

    // weight converts
    {
        long long t0 = (long long)NE * HD * GW / 4;
        wconv_kernel<<<(unsigned)((t0 + 255) / 256), 256>>>(W0, W0h, HD, GW);
        long long t1 = (long long)NE * HD * HW / 4;
        wconv_kernel<<<(unsigned)((t1 + 255) / 256), 256>>>(W1, W1h, HD, HW);
        wconv_kernel<<<(unsigned)((t1 + 255) / 256), 256>>>(W2, W2h, HD, HW);
        long long t3 = (long long)NE * OD * HD / 4;
        wconv_kernel<<<(unsigned)((t3 + 255) / 256), 256>>>(W3, W3h, OD, HD);
    }

    // gate network
    gate_gemm_kernel<<<MB / 32, 256>>>(G, GW, Wg1, bg1, H1);
    gate_gemm_kernel<<<MB / 32, 256>>>(H1, GHD, Wg2, bg2, H2);
    gate3_softmax_kernel<<<(MB * 32 + 255) / 256, 256>>>(H2, Wg3, bg3, BC);

    // layer 0: inp = G [MB,864], Kp = 6912 -> HA[:, :1024], elu
    {
        long long tot = (long long)MB * KP0 / 8;
        asplit_kernel<<<(unsigned)((tot + 255) / 256), 256>>>(G, GW, GW, BC, Ah, KP0);
        moe_hmma_gemm<<<dim3(HD / BN, MB / BM), NTHREADS, STOTAL>>>(
            Ah, W0h, KP0, b0, BC, HD, HA, HW, 1);
    }
    // layer 1: inp = HA [MB,1088], Kp = 8704 -> HB[:, :1024], elu
    {
        long long tot = (long long)MB * KP1 / 8;
        asplit_kernel<<<(unsigned)((tot + 255) / 256), 256>>>(HA, HW, HW, BC, Ah, KP1);
        moe_hmma_gemm<<<dim3(HD / BN, MB / BM), NTHREADS, STOTAL>>>(
            Ah, W1h, KP1, b1, BC, HD, HB, HW, 1);
    }
    // layer 2: inp = HB -> HA[:, :1024], elu
    {
        long long tot = (long long)MB * KP1 / 8;
        asplit_kernel<<<(unsigned)((tot + 255) / 256), 256>>>(HB, HW, HW, BC, Ah, KP1);
        moe_hmma_gemm<<<dim3(HD / BN, MB / BM), NTHREADS, STOTAL>>>(
            Ah, W2h, KP1, b2, BC, HD, HA, HW, 1);
    }
    // layer 3: inp = HA cols 0..1023 (IN=1024, lda=1088), Kp = 8192 -> out, no act
    {
        long long tot = (long long)MB * KP3 / 8;
        asplit_kernel<<<(unsigned)((tot + 255) / 256), 256>>>(HA, HW, HD, BC, Ah, KP3);
        moe_hmma_gemm<<<dim3(OD / BN, MB / BM), NTHREADS, STOTAL>>>(
            Ah, W3h, KP3, b3, BC, OD, out, OD, 0);
    }
}